// round 9
// baseline (speedup 1.0000x reference)
#include <cuda_runtime.h>
#include <cuda_bf16.h>
#include <cstddef>
#include <cstdint>

#define Nn 50000
#define Ee 800000
#define D 128
#define NODE_IN 19
#define EDGE_IN 4
#define STEPS 5
#define EPSf 1e-5f

typedef unsigned long long u64;
typedef unsigned int u32;

// ---------------- device scratch ----------------
__device__ float g_hn[Nn * D];
__device__ float g_acc[Nn * D];
__device__ float g_h[Nn * D];
__device__ float g_y[Nn * D];
__device__ float g_cnt[Nn];
__device__ float g_dis[Nn];
__device__ int   g_degi[Nn];
__device__ int   g_fill[Nn];
__device__ int   g_rowoff[Nn + 1];
__device__ int   g_csrs[Ee];
__device__ float g_csrw[Ee];
__device__ float g_bnsum[D];
__device__ float g_bnsq[D];
__device__ unsigned g_bcnt = 0;
__device__ unsigned g_bgen = 0;

#define NSLOT 17
__device__ __nv_bfloat16 g_whi[NSLOT * D * D];
__device__ __nv_bfloat16 g_wlo[NSLOT * D * D];

__device__ __forceinline__ float leaky(float v) { return v > 0.f ? v : 0.05f * v; }

__device__ __forceinline__ void red4(float* p, float a, float b, float c, float d) {
    asm volatile("red.global.add.v4.f32 [%0], {%1,%2,%3,%4};"
                 :: "l"(p), "f"(a), "f"(b), "f"(c), "f"(d) : "memory");
}
__device__ __forceinline__ void red2(float* p, float a, float b) {
    asm volatile("red.global.add.v2.f32 [%0], {%1,%2};"
                 :: "l"(p), "f"(a), "f"(b) : "memory");
}
__device__ __forceinline__ u32 bfpack(__nv_bfloat16 a, __nv_bfloat16 b) {
    __nv_bfloat162 t = __halves2bfloat162(a, b);
    return *(u32*)&t;
}
__device__ __forceinline__ u32 smem_u32(const void* p) {
    u32 a; asm("{ .reg .u64 t; cvta.to.shared.u64 t, %1; cvt.u32.u64 %0, t; }"
               : "=r"(a) : "l"(p));
    return a;
}
__device__ __forceinline__ void ldsm4(u32 addr, u32& r0, u32& r1, u32& r2, u32& r3) {
    asm volatile("ldmatrix.sync.aligned.m8n8.x4.shared.b16 {%0,%1,%2,%3}, [%4];"
                 : "=r"(r0), "=r"(r1), "=r"(r2), "=r"(r3) : "r"(addr));
}
__device__ __forceinline__ void mma16816(float* c, const u32* a, const u32* b) {
    asm volatile("mma.sync.aligned.m16n8k16.row.col.f32.bf16.bf16.f32 "
                 "{%0,%1,%2,%3}, {%4,%5,%6,%7}, {%8,%9}, {%0,%1,%2,%3};"
                 : "+f"(c[0]), "+f"(c[1]), "+f"(c[2]), "+f"(c[3])
                 : "r"(a[0]), "r"(a[1]), "r"(a[2]), "r"(a[3]), "r"(b[0]), "r"(b[1]));
}

// device-wide barrier (all gridDim.x CTAs resident: grid=148, 1 CTA/SM)
__device__ __forceinline__ void gbar() {
    __syncthreads();
    if (threadIdx.x == 0) {
        __threadfence();
        unsigned gen = atomicAdd(&g_bgen, 0u);
        unsigned v = atomicAdd(&g_bcnt, 1u);
        if (v == gridDim.x - 1) {
            atomicExch(&g_bcnt, 0u);
            __threadfence();
            atomicAdd(&g_bgen, 1u);
        } else {
            while (atomicAdd(&g_bgen, 0u) == gen) {}
        }
    }
    __syncthreads();
}

// ---------------- utility kernels ----------------
__global__ void k_zero() {
    int i = blockIdx.x * blockDim.x + threadIdx.x;
    int stride = gridDim.x * blockDim.x;
    for (int j = i; j < Nn * D; j += stride) g_acc[j] = 0.f;
    for (int j = i; j < Nn; j += stride) {
        g_cnt[j] = 0.f; g_degi[j] = 0; g_fill[j] = 0;
    }
}

__global__ void k_count(const int* __restrict__ ei) {
    int e = blockIdx.x * blockDim.x + threadIdx.x;
    if (e >= Ee) return;
    atomicAdd(&g_cnt[ei[e]], 1.f);
    atomicAdd(&g_degi[ei[Ee + e]], 1);
}

__global__ void k_scan() {
    __shared__ int ts[1024];
    int t = threadIdx.x;
    const int CH = (Nn + 1023) / 1024;
    int start = t * CH;
    int end = min(start + CH, Nn);
    int sum = 0;
    for (int i = start; i < end; i++) sum += g_degi[i];
    ts[t] = sum;
    __syncthreads();
    for (int off = 1; off < 1024; off <<= 1) {
        int v = (t >= off) ? ts[t - off] : 0;
        __syncthreads();
        ts[t] += v;
        __syncthreads();
    }
    int run = (t == 0) ? 0 : ts[t - 1];
    for (int i = start; i < end; i++) { g_rowoff[i] = run; run += g_degi[i]; }
    if (t == 1023) g_rowoff[Nn] = run;
}

__global__ void k_dis() {
    int i = blockIdx.x * blockDim.x + threadIdx.x;
    if (i < Nn) g_dis[i] = rsqrtf((float)g_degi[i] + 1.0f);
}

__global__ void k_fill(const int* __restrict__ ei) {
    int e = blockIdx.x * blockDim.x + threadIdx.x;
    if (e >= Ee) return;
    int s = ei[e], d = ei[Ee + e];
    int pos = g_rowoff[d] + atomicAdd(&g_fill[d], 1);
    g_csrs[pos] = s;
    g_csrw[pos] = g_dis[s] * g_dis[d];
}

__global__ void k_mix() {
    int i = blockIdx.x * blockDim.x + threadIdx.x;
    if (i < Nn * D) g_hn[i] += g_acc[i] / fmaxf(g_cnt[i >> 7], 1.f);
}

// all 17 weight splits: grid (64, 17)
__global__ void k_wsplit_all(
    const float* __restrict__ enW2, const float* __restrict__ enW3,
    const float* __restrict__ eeW2, const float* __restrict__ eeW3,
    const float* __restrict__ procW,
    const float* __restrict__ dW1, const float* __restrict__ dW2,
    const float* __restrict__ dW3)
{
    int slot = blockIdx.y;
    const float* W;
    if (slot == 0) W = enW2;
    else if (slot == 1) W = enW3;
    else if (slot == 2) W = eeW2;
    else if (slot == 3) W = eeW3;
    else if (slot < 14) W = procW + (size_t)(slot - 4) * D * D;
    else if (slot == 14) W = dW1;
    else if (slot == 15) W = dW2;
    else W = dW3;
    int i = blockIdx.x * 256 + threadIdx.x;
    int k = i >> 7, n = i & 127;
    float v = W[i];
    __nv_bfloat16 h = __float2bfloat16(v);
    g_whi[slot * D * D + n * D + k] = h;
    g_wlo[slot * D * D + n * D + k] = __float2bfloat16(v - __bfloat162float(h));
}

// ---------------- persistent fused MLP kernel (raw mma, R7 geometry) ----------------
// 8 warps, grid 4x2: warp = 32 rows x 64 cols. A/W 128x128 bf16, stride 136 elems.
// EPI: 0 = LN -> out; 1 = LN -> red2 scatter g_acc[esrc]; 2 = conv (g_h only)
template <int KIN, int NL, int EPI, bool BN>
__global__ void __launch_bounds__(256, 1) k_fused(
    const float* __restrict__ in,
    int slot0, int slot1, int slot2,
    const float* __restrict__ wb0, const float* __restrict__ wb1, const float* __restrict__ wb2,
    const float* __restrict__ W1, const float* __restrict__ bias1,
    const float* __restrict__ lng, const float* __restrict__ lnb,
    float* __restrict__ out, const int* __restrict__ esrc, int M, int nT)
{
    constexpr bool PRE = (NL <= 2);
    constexpr int NW = PRE ? NL : 1;
    constexpr int OFF_AL = 34816;
    constexpr int OFF_W = 69632;
    constexpr int OFF_W1S = OFF_W + NW * 69632;
    constexpr int OFF_C = OFF_W1S + (KIN > 0 ? KIN * 512 : 0);
    extern __shared__ char smem[];
    u32 sb = smem_u32(smem);

    int tid = threadIdx.x, lane = tid & 31, wid = tid >> 5;
    int wr = wid & 3, wc = wid >> 2, gid = lane >> 2, tig = lane & 3;

    float* sbias0 = (float*)(smem + OFF_C);
    float* sbias1 = (float*)(smem + OFF_C + 512);
    float* sbias2 = (float*)(smem + OFF_C + 1024);
    float* sg  = (float*)(smem + OFF_C + 1536);
    float* sl  = (float*)(smem + OFF_C + 2048);
    float* sb1 = (float*)(smem + OFF_C + 2560);
    float* rs  = (float*)(smem + OFF_C + 3072);   // [128][2]
    float* rq  = (float*)(smem + OFF_C + 4096);   // [128][2]
    float* sbias[3] = {sbias0, sbias1, sbias2};

    int slots[3] = {slot0, slot1, slot2};
    const float* wbs[3] = {wb0, wb1, wb2};

    if (tid < 128) {
        if (EPI != 2) {
            #pragma unroll
            for (int l = 0; l < NL; l++) sbias[l][tid] = wbs[l][tid];
            sg[tid] = lng[tid]; sl[tid] = lnb[tid];
        }
        if (KIN > 0) sb1[tid] = bias1[tid];
    }
    if (KIN > 0) {
        float* W1s = (float*)(smem + OFF_W1S);
        for (int i = tid; i < KIN * 128; i += 256) W1s[i] = W1[i];
    }
    if (PRE) {
        #pragma unroll
        for (int l = 0; l < NL; l++) {
            const uint4* ph = ((const uint4*)g_whi) + (size_t)slots[l] * 2048;
            const uint4* pl = ((const uint4*)g_wlo) + (size_t)slots[l] * 2048;
            char* dh = smem + OFF_W + l * 69632;
            for (int i = tid; i < 2048; i += 256) {
                int row = i >> 4, c = i & 15;
                *(uint4*)(dh + row * 272 + c * 16) = ph[row * 16 + c];
                *(uint4*)(dh + 34816 + row * 272 + c * 16) = pl[row * 16 + c];
            }
        }
    }
    __syncthreads();

    u32 a_lo = (u32)((((lane & 7) + ((lane >> 3) & 1) * 8) * 136 + (lane >> 4) * 8) * 2);
    u32 b_lo = (u32)((((lane & 7) + ((lane >> 4) & 1) * 8) * 136 + ((lane >> 3) & 1) * 8) * 2);

    for (int t = blockIdx.x; t < nT; t += gridDim.x) {
        int tb = t * 128;

        // ---- build A tile (bf16 hi/lo) ----
        if (KIN > 0) {
            float* W1s = (float*)(smem + OFF_W1S);
            int r = tid >> 1, half = tid & 1;
            int gr = min(tb + r, M - 1);
            float xv[KIN > 0 ? KIN : 1];
            #pragma unroll
            for (int k = 0; k < KIN; k++) xv[k] = in[(size_t)gr * KIN + k];
            #pragma unroll
            for (int c4 = 0; c4 < 4; c4++) {
                int cbase = half * 64 + c4 * 16;
                float a16[16];
                #pragma unroll
                for (int j = 0; j < 16; j++) a16[j] = sb1[cbase + j];
                #pragma unroll
                for (int k = 0; k < KIN; k++) {
                    float x = xv[k];
                    const float* wrow = &W1s[k * 128 + cbase];
                    #pragma unroll
                    for (int j = 0; j < 16; j++) a16[j] = fmaf(x, wrow[j], a16[j]);
                }
                #pragma unroll
                for (int j = 0; j < 16; j += 2) {
                    float z0 = leaky(a16[j]), z1 = leaky(a16[j + 1]);
                    __nv_bfloat16 h0 = __float2bfloat16(z0), h1 = __float2bfloat16(z1);
                    *(u32*)(smem + (size_t)(r * 136 + cbase + j) * 2) = bfpack(h0, h1);
                    *(u32*)(smem + OFF_AL + (size_t)(r * 136 + cbase + j) * 2) =
                        bfpack(__float2bfloat16(z0 - __bfloat162float(h0)),
                               __float2bfloat16(z1 - __bfloat162float(h1)));
                }
            }
        } else {
            for (int idx = tid; idx < 4096; idx += 256) {
                int row = idx >> 5, c4 = idx & 31;
                int gr = min(tb + row, M - 1);
                float4 v = ((const float4*)in)[(size_t)gr * 32 + c4];
                __nv_bfloat16 h0 = __float2bfloat16(v.x), h1 = __float2bfloat16(v.y);
                __nv_bfloat16 h2 = __float2bfloat16(v.z), h3 = __float2bfloat16(v.w);
                u32 hi01 = bfpack(h0, h1), hi23 = bfpack(h2, h3);
                u32 lo01 = bfpack(__float2bfloat16(v.x - __bfloat162float(h0)),
                                  __float2bfloat16(v.y - __bfloat162float(h1)));
                u32 lo23 = bfpack(__float2bfloat16(v.z - __bfloat162float(h2)),
                                  __float2bfloat16(v.w - __bfloat162float(h3)));
                *(uint2*)(smem + (size_t)(row * 136 + c4 * 4) * 2) = make_uint2(hi01, hi23);
                *(uint2*)(smem + OFF_AL + (size_t)(row * 136 + c4 * 4) * 2) = make_uint2(lo01, lo23);
            }
        }
        __syncthreads();

        // ---- layers ----
        #pragma unroll
        for (int l = 0; l < NL; l++) {
            u32 wbase;
            if (PRE) {
                wbase = sb + OFF_W + l * 69632;
            } else {
                const uint4* ph = ((const uint4*)g_whi) + (size_t)slots[l] * 2048;
                const uint4* pl = ((const uint4*)g_wlo) + (size_t)slots[l] * 2048;
                for (int i = tid; i < 2048; i += 256) {
                    int row = i >> 4, c = i & 15;
                    *(uint4*)(smem + OFF_W + row * 272 + c * 16) = ph[row * 16 + c];
                    *(uint4*)(smem + OFF_W + 34816 + row * 272 + c * 16) = pl[row * 16 + c];
                }
                __syncthreads();
                wbase = sb + OFF_W;
            }

            float acc[2][8][4];
            #pragma unroll
            for (int i = 0; i < 2; i++)
                #pragma unroll
                for (int j = 0; j < 8; j++)
                    #pragma unroll
                    for (int k = 0; k < 4; k++) acc[i][j][k] = 0.f;

            u32 ab_hi = sb + (u32)(wr * 32 * 272) + a_lo;
            u32 ab_lo = ab_hi + OFF_AL;
            u32 bb_hi = wbase + (u32)(wc * 64 * 272) + b_lo;
            u32 bb_lo = bb_hi + 34816;

            #pragma unroll
            for (int ks = 0; ks < 8; ks++) {
                u32 ah[2][4], alo[2][4];
                #pragma unroll
                for (int rt = 0; rt < 2; rt++) {
                    ldsm4(ab_hi + rt * (16 * 272) + ks * 32,
                          ah[rt][0], ah[rt][1], ah[rt][2], ah[rt][3]);
                    ldsm4(ab_lo + rt * (16 * 272) + ks * 32,
                          alo[rt][0], alo[rt][1], alo[rt][2], alo[rt][3]);
                }
                u32 bh[8][2], bl[8][2];
                #pragma unroll
                for (int np = 0; np < 4; np++) {
                    u32 r0, r1, r2, r3;
                    ldsm4(bb_hi + np * (16 * 272) + ks * 32, r0, r1, r2, r3);
                    bh[np * 2][0] = r0; bh[np * 2][1] = r1;
                    bh[np * 2 + 1][0] = r2; bh[np * 2 + 1][1] = r3;
                    ldsm4(bb_lo + np * (16 * 272) + ks * 32, r0, r1, r2, r3);
                    bl[np * 2][0] = r0; bl[np * 2][1] = r1;
                    bl[np * 2 + 1][0] = r2; bl[np * 2 + 1][1] = r3;
                }
                #pragma unroll
                for (int rt = 0; rt < 2; rt++)
                    #pragma unroll
                    for (int nt = 0; nt < 8; nt++) {
                        mma16816(acc[rt][nt], ah[rt], bh[nt]);
                        mma16816(acc[rt][nt], ah[rt], bl[nt]);
                        mma16816(acc[rt][nt], alo[rt], bh[nt]);
                    }
            }
            __syncthreads();

            if (l < NL - 1) {
                const float* bias = sbias[l];
                #pragma unroll
                for (int rt = 0; rt < 2; rt++) {
                    int r0 = wr * 32 + rt * 16 + gid;
                    #pragma unroll
                    for (int nt = 0; nt < 8; nt++) {
                        int c = wc * 64 + nt * 8 + tig * 2;
                        float b0v = bias[c], b1v = bias[c + 1];
                        float z0 = leaky(acc[rt][nt][0] + b0v);
                        float z1 = leaky(acc[rt][nt][1] + b1v);
                        float z2 = leaky(acc[rt][nt][2] + b0v);
                        float z3 = leaky(acc[rt][nt][3] + b1v);
                        __nv_bfloat16 h0 = __float2bfloat16(z0), h1 = __float2bfloat16(z1);
                        __nv_bfloat16 h2 = __float2bfloat16(z2), h3 = __float2bfloat16(z3);
                        *(u32*)(smem + (size_t)(r0 * 136 + c) * 2) = bfpack(h0, h1);
                        *(u32*)(smem + OFF_AL + (size_t)(r0 * 136 + c) * 2) =
                            bfpack(__float2bfloat16(z0 - __bfloat162float(h0)),
                                   __float2bfloat16(z1 - __bfloat162float(h1)));
                        *(u32*)(smem + (size_t)((r0 + 8) * 136 + c) * 2) = bfpack(h2, h3);
                        *(u32*)(smem + OFF_AL + (size_t)((r0 + 8) * 136 + c) * 2) =
                            bfpack(__float2bfloat16(z2 - __bfloat162float(h2)),
                                   __float2bfloat16(z3 - __bfloat162float(h3)));
                    }
                }
                __syncthreads();
            } else if (EPI == 2) {
                #pragma unroll
                for (int rt = 0; rt < 2; rt++) {
                    int r0 = wr * 32 + rt * 16 + gid;
                    int gr0 = tb + r0, gr1 = gr0 + 8;
                    #pragma unroll
                    for (int nt = 0; nt < 8; nt++) {
                        int c = wc * 64 + nt * 8 + tig * 2;
                        if (gr0 < M)
                            *(float2*)&g_h[(size_t)gr0 * D + c] =
                                make_float2(acc[rt][nt][0], acc[rt][nt][1]);
                        if (gr1 < M)
                            *(float2*)&g_h[(size_t)gr1 * D + c] =
                                make_float2(acc[rt][nt][2], acc[rt][nt][3]);
                    }
                }
                __syncthreads();
            } else {
                const float* bias = sbias[NL - 1];
                #pragma unroll
                for (int rt = 0; rt < 2; rt++) {
                    float s0 = 0.f, q0 = 0.f, s1 = 0.f, q1 = 0.f;
                    #pragma unroll
                    for (int nt = 0; nt < 8; nt++) {
                        int c = wc * 64 + nt * 8 + tig * 2;
                        float b0v = bias[c], b1v = bias[c + 1];
                        float z0 = acc[rt][nt][0] + b0v, z1 = acc[rt][nt][1] + b1v;
                        float z2 = acc[rt][nt][2] + b0v, z3 = acc[rt][nt][3] + b1v;
                        s0 += z0 + z1; q0 += z0 * z0 + z1 * z1;
                        s1 += z2 + z3; q1 += z2 * z2 + z3 * z3;
                    }
                    s0 += __shfl_xor_sync(0xffffffffu, s0, 1);
                    q0 += __shfl_xor_sync(0xffffffffu, q0, 1);
                    s1 += __shfl_xor_sync(0xffffffffu, s1, 1);
                    q1 += __shfl_xor_sync(0xffffffffu, q1, 1);
                    s0 += __shfl_xor_sync(0xffffffffu, s0, 2);
                    q0 += __shfl_xor_sync(0xffffffffu, q0, 2);
                    s1 += __shfl_xor_sync(0xffffffffu, s1, 2);
                    q1 += __shfl_xor_sync(0xffffffffu, q1, 2);
                    int r0 = wr * 32 + rt * 16 + gid;
                    if (tig == 0) {
                        rs[r0 * 2 + wc] = s0; rq[r0 * 2 + wc] = q0;
                        rs[(r0 + 8) * 2 + wc] = s1; rq[(r0 + 8) * 2 + wc] = q1;
                    }
                }
                __syncthreads();
                #pragma unroll
                for (int rt = 0; rt < 2; rt++) {
                    int r0 = wr * 32 + rt * 16 + gid;
                    float S0 = rs[r0 * 2] + rs[r0 * 2 + 1];
                    float Q0 = rq[r0 * 2] + rq[r0 * 2 + 1];
                    float S1 = rs[(r0 + 8) * 2] + rs[(r0 + 8) * 2 + 1];
                    float Q1 = rq[(r0 + 8) * 2] + rq[(r0 + 8) * 2 + 1];
                    float m0 = S0 * (1.f / (float)D);
                    float i0 = rsqrtf(Q0 * (1.f / (float)D) - m0 * m0 + EPSf);
                    float m1 = S1 * (1.f / (float)D);
                    float i1 = rsqrtf(Q1 * (1.f / (float)D) - m1 * m1 + EPSf);
                    int gr0 = tb + r0, gr1 = gr0 + 8;
                    int sidx0 = 0, sidx1 = 0;
                    if (EPI == 1) {
                        if (gr0 < M) sidx0 = esrc[gr0];
                        if (gr1 < M) sidx1 = esrc[gr1];
                    }
                    #pragma unroll
                    for (int nt = 0; nt < 8; nt++) {
                        int c = wc * 64 + nt * 8 + tig * 2;
                        float b0v = bias[c], b1v = bias[c + 1];
                        float g0 = sg[c], g1 = sg[c + 1];
                        float l0 = sl[c], l1 = sl[c + 1];
                        float o0 = (acc[rt][nt][0] + b0v - m0) * i0 * g0 + l0;
                        float o1 = (acc[rt][nt][1] + b1v - m0) * i0 * g1 + l1;
                        float o2 = (acc[rt][nt][2] + b0v - m1) * i1 * g0 + l0;
                        float o3 = (acc[rt][nt][3] + b1v - m1) * i1 * g1 + l1;
                        if (EPI == 0) {
                            if (gr0 < M) *(float2*)&out[(size_t)gr0 * D + c] = make_float2(o0, o1);
                            if (gr1 < M) *(float2*)&out[(size_t)gr1 * D + c] = make_float2(o2, o3);
                        } else {
                            if (gr0 < M) red2(&g_acc[(size_t)sidx0 * D + c], o0, o1);
                            if (gr1 < M) red2(&g_acc[(size_t)sidx1 * D + c], o2, o3);
                        }
                    }
                }
                __syncthreads();
            }
        }
    }
}

// ---------------- fused processor: 5 steps, persistent, device-wide barriers ----------------
// smem: A tile [0,69632) | W [69632,139264) | consts at 139264
#define P_OFF_AL 34816
#define P_OFF_W 69632
#define P_OFF_C 139264
#define SM_PROC (139264 + 2048)

template <bool BN>
__device__ __forceinline__ void conv_tiles(
    char* smem, u32 sb, const float* __restrict__ src, int slot,
    const float* sbns, const float* sbnf,
    int tid, int wr, int wc, int gid, int tig, u32 a_lo, u32 b_lo)
{
    // load W (hi/lo) for this conv
    const uint4* ph = ((const uint4*)g_whi) + (size_t)slot * 2048;
    const uint4* pl = ((const uint4*)g_wlo) + (size_t)slot * 2048;
    for (int i = tid; i < 2048; i += 256) {
        int row = i >> 4, c = i & 15;
        *(uint4*)(smem + P_OFF_W + row * 272 + c * 16) = ph[row * 16 + c];
        *(uint4*)(smem + P_OFF_W + 34816 + row * 272 + c * 16) = pl[row * 16 + c];
    }
    __syncthreads();

    const int nT = (Nn + 127) / 128;
    for (int t = blockIdx.x; t < nT; t += gridDim.x) {
        int tb = t * 128;
        for (int idx = tid; idx < 4096; idx += 256) {
            int row = idx >> 5, c4 = idx & 31;
            int gr = min(tb + row, Nn - 1);
            float4 v = ((const float4*)src)[(size_t)gr * 32 + c4];
            if (BN) {
                int c = c4 * 4;
                v.x = fmaf(v.x, sbns[c],     sbnf[c]);
                v.y = fmaf(v.y, sbns[c + 1], sbnf[c + 1]);
                v.z = fmaf(v.z, sbns[c + 2], sbnf[c + 2]);
                v.w = fmaf(v.w, sbns[c + 3], sbnf[c + 3]);
            }
            __nv_bfloat16 h0 = __float2bfloat16(v.x), h1 = __float2bfloat16(v.y);
            __nv_bfloat16 h2 = __float2bfloat16(v.z), h3 = __float2bfloat16(v.w);
            u32 hi01 = bfpack(h0, h1), hi23 = bfpack(h2, h3);
            u32 lo01 = bfpack(__float2bfloat16(v.x - __bfloat162float(h0)),
                              __float2bfloat16(v.y - __bfloat162float(h1)));
            u32 lo23 = bfpack(__float2bfloat16(v.z - __bfloat162float(h2)),
                              __float2bfloat16(v.w - __bfloat162float(h3)));
            *(uint2*)(smem + (size_t)(row * 136 + c4 * 4) * 2) = make_uint2(hi01, hi23);
            *(uint2*)(smem + P_OFF_AL + (size_t)(row * 136 + c4 * 4) * 2) = make_uint2(lo01, lo23);
        }
        __syncthreads();

        float acc[2][8][4];
        #pragma unroll
        for (int i = 0; i < 2; i++)
            #pragma unroll
            for (int j = 0; j < 8; j++)
                #pragma unroll
                for (int k = 0; k < 4; k++) acc[i][j][k] = 0.f;

        u32 ab_hi = sb + (u32)(wr * 32 * 272) + a_lo;
        u32 ab_lo = ab_hi + P_OFF_AL;
        u32 bb_hi = sb + P_OFF_W + (u32)(wc * 64 * 272) + b_lo;
        u32 bb_lo = bb_hi + 34816;

        #pragma unroll
        for (int ks = 0; ks < 8; ks++) {
            u32 ah[2][4], alo[2][4];
            #pragma unroll
            for (int rt = 0; rt < 2; rt++) {
                ldsm4(ab_hi + rt * (16 * 272) + ks * 32,
                      ah[rt][0], ah[rt][1], ah[rt][2], ah[rt][3]);
                ldsm4(ab_lo + rt * (16 * 272) + ks * 32,
                      alo[rt][0], alo[rt][1], alo[rt][2], alo[rt][3]);
            }
            u32 bh[8][2], bl[8][2];
            #pragma unroll
            for (int np = 0; np < 4; np++) {
                u32 r0, r1, r2, r3;
                ldsm4(bb_hi + np * (16 * 272) + ks * 32, r0, r1, r2, r3);
                bh[np * 2][0] = r0; bh[np * 2][1] = r1;
                bh[np * 2 + 1][0] = r2; bh[np * 2 + 1][1] = r3;
                ldsm4(bb_lo + np * (16 * 272) + ks * 32, r0, r1, r2, r3);
                bl[np * 2][0] = r0; bl[np * 2][1] = r1;
                bl[np * 2 + 1][0] = r2; bl[np * 2 + 1][1] = r3;
            }
            #pragma unroll
            for (int rt = 0; rt < 2; rt++)
                #pragma unroll
                for (int nt = 0; nt < 8; nt++) {
                    mma16816(acc[rt][nt], ah[rt], bh[nt]);
                    mma16816(acc[rt][nt], ah[rt], bl[nt]);
                    mma16816(acc[rt][nt], alo[rt], bh[nt]);
                }
        }
        __syncthreads();

        #pragma unroll
        for (int rt = 0; rt < 2; rt++) {
            int r0 = wr * 32 + rt * 16 + gid;
            int gr0 = tb + r0, gr1 = gr0 + 8;
            #pragma unroll
            for (int nt = 0; nt < 8; nt++) {
                int c = wc * 64 + nt * 8 + tig * 2;
                if (gr0 < Nn)
                    *(float2*)&g_h[(size_t)gr0 * D + c] =
                        make_float2(acc[rt][nt][0], acc[rt][nt][1]);
                if (gr1 < Nn)
                    *(float2*)&g_h[(size_t)gr1 * D + c] =
                        make_float2(acc[rt][nt][2], acc[rt][nt][3]);
            }
        }
        __syncthreads();
    }
}

// gather agg = h[node]*dis^2 + sum h[src]*w  (4-edge unroll)
__device__ __forceinline__ float4 gather_node(int node, int c0) {
    float dd = g_dis[node];
    float d2 = dd * dd;
    float4 a = *(const float4*)&g_h[(size_t)node * D + c0];
    a.x *= d2; a.y *= d2; a.z *= d2; a.w *= d2;
    int p = g_rowoff[node], p1 = g_rowoff[node + 1];
    for (; p + 3 < p1; p += 4) {
        int sA = g_csrs[p];     float wA = g_csrw[p];
        int sB = g_csrs[p + 1]; float wB = g_csrw[p + 1];
        int sC = g_csrs[p + 2]; float wC = g_csrw[p + 2];
        int sD = g_csrs[p + 3]; float wD = g_csrw[p + 3];
        float4 vA = *(const float4*)&g_h[(size_t)sA * D + c0];
        float4 vB = *(const float4*)&g_h[(size_t)sB * D + c0];
        float4 vC = *(const float4*)&g_h[(size_t)sC * D + c0];
        float4 vD = *(const float4*)&g_h[(size_t)sD * D + c0];
        a.x = fmaf(vA.x, wA, a.x); a.y = fmaf(vA.y, wA, a.y);
        a.z = fmaf(vA.z, wA, a.z); a.w = fmaf(vA.w, wA, a.w);
        a.x = fmaf(vB.x, wB, a.x); a.y = fmaf(vB.y, wB, a.y);
        a.z = fmaf(vB.z, wB, a.z); a.w = fmaf(vB.w, wB, a.w);
        a.x = fmaf(vC.x, wC, a.x); a.y = fmaf(vC.y, wC, a.y);
        a.z = fmaf(vC.z, wC, a.z); a.w = fmaf(vC.w, wC, a.w);
        a.x = fmaf(vD.x, wD, a.x); a.y = fmaf(vD.y, wD, a.y);
        a.z = fmaf(vD.z, wD, a.z); a.w = fmaf(vD.w, wD, a.w);
    }
    for (; p < p1; p++) {
        int sA = g_csrs[p]; float wA = g_csrw[p];
        float4 vA = *(const float4*)&g_h[(size_t)sA * D + c0];
        a.x = fmaf(vA.x, wA, a.x); a.y = fmaf(vA.y, wA, a.y);
        a.z = fmaf(vA.z, wA, a.z); a.w = fmaf(vA.w, wA, a.w);
    }
    return a;
}

__global__ void __launch_bounds__(256, 1) k_proc(
    const float* __restrict__ procb, const float* __restrict__ bng,
    const float* __restrict__ bnb)
{
    extern __shared__ char smem[];
    u32 sb = smem_u32(smem);
    int tid = threadIdx.x, lane = tid & 31, wid = tid >> 5;
    int wr = wid & 3, wc = wid >> 2, gid = lane >> 2, tig = lane & 3;
    int c0 = lane * 4;
    int gw = blockIdx.x * 8 + wid;
    int nw = gridDim.x * 8;

    float* sb0  = (float*)(smem + P_OFF_C);
    float* sb1c = (float*)(smem + P_OFF_C + 512);
    float* sbns = (float*)(smem + P_OFF_C + 1024);
    float* sbnf = (float*)(smem + P_OFF_C + 1536);

    u32 a_lo = (u32)((((lane & 7) + ((lane >> 3) & 1) * 8) * 136 + (lane >> 4) * 8) * 2);
    u32 b_lo = (u32)((((lane & 7) + ((lane >> 4) & 1) * 8) * 136 + ((lane >> 3) & 1) * 8) * 2);

    float* hn_ptr = g_hn;
    float* y_ptr = g_y;

    for (int s = 0; s < STEPS; s++) {
        if (tid < 128) {
            sb0[tid]  = procb[(size_t)(2 * s) * D + tid];
            sb1c[tid] = procb[(size_t)(2 * s + 1) * D + tid];
        }
        if (blockIdx.x == 0 && tid < 128) { g_bnsum[tid] = 0.f; g_bnsq[tid] = 0.f; }

        // conv1: g_h = hn @ W0
        conv_tiles<false>(smem, sb, hn_ptr, 4 + 2 * s, nullptr, nullptr,
                          tid, wr, wc, gid, tig, a_lo, b_lo);
        gbar();

        // gatherA: y = leaky(agg + b0); BN stats
        {
            float4 bb = *(const float4*)&sb0[c0];
            float s0 = 0.f, s1 = 0.f, s2 = 0.f, s3 = 0.f;
            float q0 = 0.f, q1 = 0.f, q2 = 0.f, q3 = 0.f;
            for (int node = gw; node < Nn; node += nw) {
                float4 a = gather_node(node, c0);
                float v0 = leaky(a.x + bb.x), v1 = leaky(a.y + bb.y);
                float v2 = leaky(a.z + bb.z), v3 = leaky(a.w + bb.w);
                *(float4*)&y_ptr[(size_t)node * D + c0] = make_float4(v0, v1, v2, v3);
                s0 += v0; s1 += v1; s2 += v2; s3 += v3;
                q0 += v0 * v0; q1 += v1 * v1; q2 += v2 * v2; q3 += v3 * v3;
            }
            red4(&g_bnsum[c0], s0, s1, s2, s3);
            red4(&g_bnsq[c0],  q0, q1, q2, q3);
        }
        gbar();

        // BN finalize (per-CTA, into smem)
        if (tid < 128) {
            float m = g_bnsum[tid] * (1.f / (float)Nn);
            float v = g_bnsq[tid] * (1.f / (float)Nn) - m * m;
            float sc = bng[(size_t)s * D + tid] * rsqrtf(v + EPSf);
            sbns[tid] = sc;
            sbnf[tid] = bnb[(size_t)s * D + tid] - m * sc;
        }
        __syncthreads();

        // conv2: g_h = BN(y) @ W1
        conv_tiles<true>(smem, sb, y_ptr, 5 + 2 * s, sbns, sbnf,
                         tid, wr, wc, gid, tig, a_lo, b_lo);
        gbar();

        // gatherB: hn += agg + b1
        {
            float4 bb = *(const float4*)&sb1c[c0];
            for (int node = gw; node < Nn; node += nw) {
                float4 a = gather_node(node, c0);
                float4 h4 = *(const float4*)&hn_ptr[(size_t)node * D + c0];
                h4.x += a.x + bb.x; h4.y += a.y + bb.y;
                h4.z += a.z + bb.z; h4.w += a.w + bb.w;
                *(float4*)&hn_ptr[(size_t)node * D + c0] = h4;
            }
        }
        gbar();
    }
}

// ---------------- host orchestration ----------------
extern "C" void kernel_launch(void* const* d_in, const int* in_sizes, int n_in,
                              void* d_out, int out_size)
{
    const float* node_feat = (const float*)d_in[0];
    const float* edge_feat = (const float*)d_in[1];
    const int*   ei        = (const int*)d_in[2];
    const float* enW1 = (const float*)d_in[3];  const float* enb1 = (const float*)d_in[4];
    const float* enW2 = (const float*)d_in[5];  const float* enb2 = (const float*)d_in[6];
    const float* enW3 = (const float*)d_in[7];  const float* enb3 = (const float*)d_in[8];
    const float* enlg = (const float*)d_in[9];  const float* enlb = (const float*)d_in[10];
    const float* eeW1 = (const float*)d_in[11]; const float* eeb1 = (const float*)d_in[12];
    const float* eeW2 = (const float*)d_in[13]; const float* eeb2 = (const float*)d_in[14];
    const float* eeW3 = (const float*)d_in[15]; const float* eeb3 = (const float*)d_in[16];
    const float* eelg = (const float*)d_in[17]; const float* eelb = (const float*)d_in[18];
    const float* procW = (const float*)d_in[19];
    const float* procb = (const float*)d_in[20];
    const float* bng   = (const float*)d_in[21];
    const float* bnb   = (const float*)d_in[22];
    const float* dW1 = (const float*)d_in[23]; const float* db1 = (const float*)d_in[24];
    const float* dW2 = (const float*)d_in[25]; const float* db2 = (const float*)d_in[26];
    const float* dW3 = (const float*)d_in[27]; const float* db3 = (const float*)d_in[28];
    const float* dlg = (const float*)d_in[29]; const float* dlb = (const float*)d_in[30];
    float* out = (float*)d_out;

    float* hn_ptr = nullptr; cudaGetSymbolAddress((void**)&hn_ptr, g_hn);

    const int SM_EDGE = 69632 + 2 * 69632 + EDGE_IN * 512 + 5120;   // 216064
    const int SM_NODE = 69632 + 2 * 69632 + NODE_IN * 512 + 5120;   // 223744
    const int SM_DEC  = 69632 + 1 * 69632 + 5120;                    // 144384

    cudaFuncSetAttribute(k_fused<EDGE_IN, 2, 1, false>, cudaFuncAttributeMaxDynamicSharedMemorySize, SM_EDGE);
    cudaFuncSetAttribute(k_fused<NODE_IN, 2, 0, false>, cudaFuncAttributeMaxDynamicSharedMemorySize, SM_NODE);
    cudaFuncSetAttribute(k_fused<0, 3, 0, false>, cudaFuncAttributeMaxDynamicSharedMemorySize, SM_DEC);
    cudaFuncSetAttribute(k_proc, cudaFuncAttributeMaxDynamicSharedMemorySize, SM_PROC);

    int NnT = (Nn + 127) / 128, EeT = Ee / 128;
    int G = 148;

    // 1: weight splits   2: zero   3: count
    k_wsplit_all<<<dim3(64, NSLOT), 256>>>(enW2, enW3, eeW2, eeW3, procW, dW1, dW2, dW3);
    k_zero<<<512, 256>>>();
    k_count<<<(Ee + 255) / 256, 256>>>(ei);
    // 4: edge encoder (profiled) — LN + scatter-sum into g_acc
    k_fused<EDGE_IN, 2, 1, false><<<G, 256, SM_EDGE>>>(
        edge_feat, 2, 3, 0, eeb2, eeb3, nullptr, eeW1, eeb1, eelg, eelb,
        nullptr, ei, Ee, EeT);
    // 5: node encoder
    k_fused<NODE_IN, 2, 0, false><<<G, 256, SM_NODE>>>(
        node_feat, 0, 1, 0, enb2, enb3, nullptr, enW1, enb1, enlg, enlb,
        hn_ptr, nullptr, Nn, NnT);
    // CSR build + mix
    k_scan<<<1, 1024>>>();
    k_dis<<<(Nn + 255) / 256, 256>>>();
    k_fill<<<(Ee + 255) / 256, 256>>>(ei);
    k_mix<<<(Nn * D + 255) / 256, 256>>>();

    // all 5 processor steps in one persistent launch
    k_proc<<<G, 256, SM_PROC>>>(procb, bng, bnb);

    // decoder (3 layers + LN, per-layer W reload)
    k_fused<0, 3, 0, false><<<G, 256, SM_DEC>>>(
        hn_ptr, 14, 15, 16, db1, db2, db3,
        nullptr, nullptr, dlg, dlb, out, nullptr, Nn, NnT);
}

// round 10
// speedup vs baseline: 1.3227x; 1.3227x over previous
#include <cuda_runtime.h>
#include <cuda_bf16.h>
#include <cstddef>
#include <cstdint>

#define Nn 50000
#define Ee 800000
#define D 128
#define NODE_IN 19
#define EDGE_IN 4
#define STEPS 5
#define EPSf 1e-5f

typedef unsigned long long u64;
typedef unsigned int u32;

// ---------------- device scratch ----------------
__device__ float g_hn[Nn * D];
__device__ float g_acc[Nn * D];
__device__ float g_h[Nn * D];
__device__ float g_y[Nn * D];
__device__ float g_cnt[Nn];
__device__ float g_dis[Nn];
__device__ int   g_degi[Nn];
__device__ int   g_fill[Nn];
__device__ int   g_rowoff[Nn + 1];
__device__ int   g_csrs[Ee];
__device__ float g_csrw[Ee];
__device__ float g_bnsum[STEPS][D];
__device__ float g_bnsq[STEPS][D];

#define NSLOT 17
__device__ __nv_bfloat16 g_whi[NSLOT * D * D];
__device__ __nv_bfloat16 g_wlo[NSLOT * D * D];

__device__ __forceinline__ float leaky(float v) { return v > 0.f ? v : 0.05f * v; }

__device__ __forceinline__ void red4(float* p, float a, float b, float c, float d) {
    asm volatile("red.global.add.v4.f32 [%0], {%1,%2,%3,%4};"
                 :: "l"(p), "f"(a), "f"(b), "f"(c), "f"(d) : "memory");
}
__device__ __forceinline__ void red2(float* p, float a, float b) {
    asm volatile("red.global.add.v2.f32 [%0], {%1,%2};"
                 :: "l"(p), "f"(a), "f"(b) : "memory");
}
__device__ __forceinline__ u32 bfpack(__nv_bfloat16 a, __nv_bfloat16 b) {
    __nv_bfloat162 t = __halves2bfloat162(a, b);
    return *(u32*)&t;
}
__device__ __forceinline__ u32 smem_u32(const void* p) {
    u32 a; asm("{ .reg .u64 t; cvta.to.shared.u64 t, %1; cvt.u32.u64 %0, t; }"
               : "=r"(a) : "l"(p));
    return a;
}
__device__ __forceinline__ void ldsm4(u32 addr, u32& r0, u32& r1, u32& r2, u32& r3) {
    asm volatile("ldmatrix.sync.aligned.m8n8.x4.shared.b16 {%0,%1,%2,%3}, [%4];"
                 : "=r"(r0), "=r"(r1), "=r"(r2), "=r"(r3) : "r"(addr));
}
__device__ __forceinline__ void mma16816(float* c, const u32* a, const u32* b) {
    asm volatile("mma.sync.aligned.m16n8k16.row.col.f32.bf16.bf16.f32 "
                 "{%0,%1,%2,%3}, {%4,%5,%6,%7}, {%8,%9}, {%0,%1,%2,%3};"
                 : "+f"(c[0]), "+f"(c[1]), "+f"(c[2]), "+f"(c[3])
                 : "r"(a[0]), "r"(a[1]), "r"(a[2]), "r"(a[3]), "r"(b[0]), "r"(b[1]));
}

// ---------------- utility kernels ----------------
__global__ void k_zero() {
    int i = blockIdx.x * blockDim.x + threadIdx.x;
    int stride = gridDim.x * blockDim.x;
    for (int j = i; j < Nn * D; j += stride) g_acc[j] = 0.f;
    for (int j = i; j < Nn; j += stride) {
        g_cnt[j] = 0.f; g_degi[j] = 0; g_fill[j] = 0;
    }
    if (i < STEPS * D) { (&g_bnsum[0][0])[i] = 0.f; (&g_bnsq[0][0])[i] = 0.f; }
}

__global__ void k_count(const int* __restrict__ ei) {
    int e = blockIdx.x * blockDim.x + threadIdx.x;
    if (e >= Ee) return;
    atomicAdd(&g_cnt[ei[e]], 1.f);
    atomicAdd(&g_degi[ei[Ee + e]], 1);
}

__global__ void k_scan() {
    __shared__ int ts[1024];
    int t = threadIdx.x;
    const int CH = (Nn + 1023) / 1024;
    int start = t * CH;
    int end = min(start + CH, Nn);
    int sum = 0;
    for (int i = start; i < end; i++) sum += g_degi[i];
    ts[t] = sum;
    __syncthreads();
    for (int off = 1; off < 1024; off <<= 1) {
        int v = (t >= off) ? ts[t - off] : 0;
        __syncthreads();
        ts[t] += v;
        __syncthreads();
    }
    int run = (t == 0) ? 0 : ts[t - 1];
    for (int i = start; i < end; i++) { g_rowoff[i] = run; run += g_degi[i]; }
    if (t == 1023) g_rowoff[Nn] = run;
}

__global__ void k_dis() {
    int i = blockIdx.x * blockDim.x + threadIdx.x;
    if (i < Nn) g_dis[i] = rsqrtf((float)g_degi[i] + 1.0f);
}

__global__ void k_fill(const int* __restrict__ ei) {
    int e = blockIdx.x * blockDim.x + threadIdx.x;
    if (e >= Ee) return;
    int s = ei[e], d = ei[Ee + e];
    int pos = g_rowoff[d] + atomicAdd(&g_fill[d], 1);
    g_csrs[pos] = s;
    g_csrw[pos] = g_dis[s] * g_dis[d];
}

// ---------------- CSR gather kernels (warp per node, 4-edge unroll) ----------------
__device__ __forceinline__ float4 gather_node(int node, int c0) {
    float dd = g_dis[node];
    float d2 = dd * dd;
    float4 a = *(const float4*)&g_h[(size_t)node * D + c0];
    a.x *= d2; a.y *= d2; a.z *= d2; a.w *= d2;
    int p = g_rowoff[node], p1 = g_rowoff[node + 1];
    for (; p + 3 < p1; p += 4) {
        int sA = g_csrs[p];     float wA = g_csrw[p];
        int sB = g_csrs[p + 1]; float wB = g_csrw[p + 1];
        int sC = g_csrs[p + 2]; float wC = g_csrw[p + 2];
        int sD = g_csrs[p + 3]; float wD = g_csrw[p + 3];
        float4 vA = *(const float4*)&g_h[(size_t)sA * D + c0];
        float4 vB = *(const float4*)&g_h[(size_t)sB * D + c0];
        float4 vC = *(const float4*)&g_h[(size_t)sC * D + c0];
        float4 vD = *(const float4*)&g_h[(size_t)sD * D + c0];
        a.x = fmaf(vA.x, wA, a.x); a.y = fmaf(vA.y, wA, a.y);
        a.z = fmaf(vA.z, wA, a.z); a.w = fmaf(vA.w, wA, a.w);
        a.x = fmaf(vB.x, wB, a.x); a.y = fmaf(vB.y, wB, a.y);
        a.z = fmaf(vB.z, wB, a.z); a.w = fmaf(vB.w, wB, a.w);
        a.x = fmaf(vC.x, wC, a.x); a.y = fmaf(vC.y, wC, a.y);
        a.z = fmaf(vC.z, wC, a.z); a.w = fmaf(vC.w, wC, a.w);
        a.x = fmaf(vD.x, wD, a.x); a.y = fmaf(vD.y, wD, a.y);
        a.z = fmaf(vD.z, wD, a.z); a.w = fmaf(vD.w, wD, a.w);
    }
    for (; p < p1; p++) {
        int sA = g_csrs[p]; float wA = g_csrw[p];
        float4 vA = *(const float4*)&g_h[(size_t)sA * D + c0];
        a.x = fmaf(vA.x, wA, a.x); a.y = fmaf(vA.y, wA, a.y);
        a.z = fmaf(vA.z, wA, a.z); a.w = fmaf(vA.w, wA, a.w);
    }
    return a;
}

__global__ void __launch_bounds__(256) k_gatherA(const float* __restrict__ b0, int step) {
    int lane = threadIdx.x & 31;
    int gw = blockIdx.x * 8 + (threadIdx.x >> 5);
    int nw = gridDim.x * 8;
    int c0 = lane * 4;
    float4 bb = *(const float4*)&b0[c0];
    float s0 = 0.f, s1 = 0.f, s2 = 0.f, s3 = 0.f;
    float q0 = 0.f, q1 = 0.f, q2 = 0.f, q3 = 0.f;

    for (int node = gw; node < Nn; node += nw) {
        float4 a = gather_node(node, c0);
        float v0 = leaky(a.x + bb.x), v1 = leaky(a.y + bb.y);
        float v2 = leaky(a.z + bb.z), v3 = leaky(a.w + bb.w);
        *(float4*)&g_y[(size_t)node * D + c0] = make_float4(v0, v1, v2, v3);
        s0 += v0; s1 += v1; s2 += v2; s3 += v3;
        q0 += v0 * v0; q1 += v1 * v1; q2 += v2 * v2; q3 += v3 * v3;
    }
    red4(&g_bnsum[step][c0], s0, s1, s2, s3);
    red4(&g_bnsq[step][c0],  q0, q1, q2, q3);
}

__global__ void __launch_bounds__(256) k_gatherB(const float* __restrict__ b1) {
    int lane = threadIdx.x & 31;
    int gw = blockIdx.x * 8 + (threadIdx.x >> 5);
    int nw = gridDim.x * 8;
    int c0 = lane * 4;
    float4 bb = *(const float4*)&b1[c0];

    for (int node = gw; node < Nn; node += nw) {
        float4 a = gather_node(node, c0);
        float4 h4 = *(const float4*)&g_hn[(size_t)node * D + c0];
        h4.x += a.x + bb.x; h4.y += a.y + bb.y;
        h4.z += a.z + bb.z; h4.w += a.w + bb.w;
        *(float4*)&g_hn[(size_t)node * D + c0] = h4;
    }
}

// all 17 weight splits: grid (64, 17)
__global__ void k_wsplit_all(
    const float* __restrict__ enW2, const float* __restrict__ enW3,
    const float* __restrict__ eeW2, const float* __restrict__ eeW3,
    const float* __restrict__ procW,
    const float* __restrict__ dW1, const float* __restrict__ dW2,
    const float* __restrict__ dW3)
{
    int slot = blockIdx.y;
    const float* W;
    if (slot == 0) W = enW2;
    else if (slot == 1) W = enW3;
    else if (slot == 2) W = eeW2;
    else if (slot == 3) W = eeW3;
    else if (slot < 14) W = procW + (size_t)(slot - 4) * D * D;
    else if (slot == 14) W = dW1;
    else if (slot == 15) W = dW2;
    else W = dW3;
    int i = blockIdx.x * 256 + threadIdx.x;
    int k = i >> 7, n = i & 127;
    float v = W[i];
    __nv_bfloat16 h = __float2bfloat16(v);
    g_whi[slot * D * D + n * D + k] = h;
    g_wlo[slot * D * D + n * D + k] = __float2bfloat16(v - __bfloat162float(h));
}

// ---------------- persistent fused MLP kernel (raw mma, R7 geometry) ----------------
// 8 warps, grid 4x2: warp = 32 rows x 64 cols. A/W 128x128 bf16, stride 136 elems.
// EPI: 0 = LN -> out; 1 = LN -> red2 scatter g_acc[esrc]; 2 = conv (g_h only);
//      3 = LN + scatter-mean mix -> out (node encoder)
// BN: conv input affine from BN stats (finalized in-kernel); BNSTEP = which slot.
template <int KIN, int NL, int EPI, bool BN>
__global__ void __launch_bounds__(256, 1) k_fused(
    const float* __restrict__ in,
    int slot0, int slot1, int slot2,
    const float* __restrict__ wb0, const float* __restrict__ wb1, const float* __restrict__ wb2,
    const float* __restrict__ W1, const float* __restrict__ bias1,
    const float* __restrict__ lng, const float* __restrict__ lnb,
    float* __restrict__ out, const int* __restrict__ esrc, int M, int nT,
    int bnstep, const float* __restrict__ bng, const float* __restrict__ bnb)
{
    constexpr bool PRE = (NL <= 2);
    constexpr int NW = PRE ? NL : 1;
    constexpr int OFF_AL = 34816;
    constexpr int OFF_W = 69632;
    constexpr int OFF_W1S = OFF_W + NW * 69632;
    constexpr int OFF_C = OFF_W1S + (KIN > 0 ? KIN * 512 : 0);
    extern __shared__ char smem[];
    u32 sb = smem_u32(smem);

    int tid = threadIdx.x, lane = tid & 31, wid = tid >> 5;
    int wr = wid & 3, wc = wid >> 2, gid = lane >> 2, tig = lane & 3;

    float* sbias0 = (float*)(smem + OFF_C);
    float* sbias1 = (float*)(smem + OFF_C + 512);
    float* sbias2 = (float*)(smem + OFF_C + 1024);
    float* sg  = (float*)(smem + OFF_C + 1536);
    float* sl  = (float*)(smem + OFF_C + 2048);
    float* sb1 = (float*)(smem + OFF_C + 2560);
    float* rs  = (float*)(smem + OFF_C + 3072);   // [128][2]
    float* rq  = (float*)(smem + OFF_C + 4096);   // [128][2]
    float* sbns = (float*)(smem + OFF_C + 5120);  // BN scale
    float* sbnf = (float*)(smem + OFF_C + 5632);  // BN shift
    float* sbias[3] = {sbias0, sbias1, sbias2};

    int slots[3] = {slot0, slot1, slot2};
    const float* wbs[3] = {wb0, wb1, wb2};

    if (tid < 128) {
        if (EPI != 2) {
            #pragma unroll
            for (int l = 0; l < NL; l++) sbias[l][tid] = wbs[l][tid];
            sg[tid] = lng[tid]; sl[tid] = lnb[tid];
        }
        if (KIN > 0) sb1[tid] = bias1[tid];
        if (BN) {
            float m = g_bnsum[bnstep][tid] * (1.f / (float)Nn);
            float v = g_bnsq[bnstep][tid] * (1.f / (float)Nn) - m * m;
            float sc = bng[tid] * rsqrtf(v + EPSf);
            sbns[tid] = sc;
            sbnf[tid] = bnb[tid] - m * sc;
        }
    }
    if (KIN > 0) {
        float* W1s = (float*)(smem + OFF_W1S);
        for (int i = tid; i < KIN * 128; i += 256) W1s[i] = W1[i];
    }
    if (PRE) {
        #pragma unroll
        for (int l = 0; l < NL; l++) {
            const uint4* ph = ((const uint4*)g_whi) + (size_t)slots[l] * 2048;
            const uint4* pl = ((const uint4*)g_wlo) + (size_t)slots[l] * 2048;
            char* dh = smem + OFF_W + l * 69632;
            for (int i = tid; i < 2048; i += 256) {
                int row = i >> 4, c = i & 15;
                *(uint4*)(dh + row * 272 + c * 16) = ph[row * 16 + c];
                *(uint4*)(dh + 34816 + row * 272 + c * 16) = pl[row * 16 + c];
            }
        }
    }
    __syncthreads();

    u32 a_lo = (u32)((((lane & 7) + ((lane >> 3) & 1) * 8) * 136 + (lane >> 4) * 8) * 2);
    u32 b_lo = (u32)((((lane & 7) + ((lane >> 4) & 1) * 8) * 136 + ((lane >> 3) & 1) * 8) * 2);

    for (int t = blockIdx.x; t < nT; t += gridDim.x) {
        int tb = t * 128;

        // ---- build A tile (bf16 hi/lo) ----
        if (KIN > 0) {
            float* W1s = (float*)(smem + OFF_W1S);
            int r = tid >> 1, half = tid & 1;
            int gr = min(tb + r, M - 1);
            float xv[KIN > 0 ? KIN : 1];
            #pragma unroll
            for (int k = 0; k < KIN; k++) xv[k] = in[(size_t)gr * KIN + k];
            #pragma unroll
            for (int c4 = 0; c4 < 4; c4++) {
                int cbase = half * 64 + c4 * 16;
                float a16[16];
                #pragma unroll
                for (int j = 0; j < 16; j++) a16[j] = sb1[cbase + j];
                #pragma unroll
                for (int k = 0; k < KIN; k++) {
                    float x = xv[k];
                    const float* wrow = &W1s[k * 128 + cbase];
                    #pragma unroll
                    for (int j = 0; j < 16; j++) a16[j] = fmaf(x, wrow[j], a16[j]);
                }
                #pragma unroll
                for (int j = 0; j < 16; j += 2) {
                    float z0 = leaky(a16[j]), z1 = leaky(a16[j + 1]);
                    __nv_bfloat16 h0 = __float2bfloat16(z0), h1 = __float2bfloat16(z1);
                    *(u32*)(smem + (size_t)(r * 136 + cbase + j) * 2) = bfpack(h0, h1);
                    *(u32*)(smem + OFF_AL + (size_t)(r * 136 + cbase + j) * 2) =
                        bfpack(__float2bfloat16(z0 - __bfloat162float(h0)),
                               __float2bfloat16(z1 - __bfloat162float(h1)));
                }
            }
        } else {
            for (int idx = tid; idx < 4096; idx += 256) {
                int row = idx >> 5, c4 = idx & 31;
                int gr = min(tb + row, M - 1);
                float4 v = ((const float4*)in)[(size_t)gr * 32 + c4];
                if (BN) {
                    int c = c4 * 4;
                    v.x = fmaf(v.x, sbns[c],     sbnf[c]);
                    v.y = fmaf(v.y, sbns[c + 1], sbnf[c + 1]);
                    v.z = fmaf(v.z, sbns[c + 2], sbnf[c + 2]);
                    v.w = fmaf(v.w, sbns[c + 3], sbnf[c + 3]);
                }
                __nv_bfloat16 h0 = __float2bfloat16(v.x), h1 = __float2bfloat16(v.y);
                __nv_bfloat16 h2 = __float2bfloat16(v.z), h3 = __float2bfloat16(v.w);
                u32 hi01 = bfpack(h0, h1), hi23 = bfpack(h2, h3);
                u32 lo01 = bfpack(__float2bfloat16(v.x - __bfloat162float(h0)),
                                  __float2bfloat16(v.y - __bfloat162float(h1)));
                u32 lo23 = bfpack(__float2bfloat16(v.z - __bfloat162float(h2)),
                                  __float2bfloat16(v.w - __bfloat162float(h3)));
                *(uint2*)(smem + (size_t)(row * 136 + c4 * 4) * 2) = make_uint2(hi01, hi23);
                *(uint2*)(smem + OFF_AL + (size_t)(row * 136 + c4 * 4) * 2) = make_uint2(lo01, lo23);
            }
        }
        __syncthreads();

        // ---- layers ----
        #pragma unroll
        for (int l = 0; l < NL; l++) {
            u32 wbase;
            if (PRE) {
                wbase = sb + OFF_W + l * 69632;
            } else {
                const uint4* ph = ((const uint4*)g_whi) + (size_t)slots[l] * 2048;
                const uint4* pl = ((const uint4*)g_wlo) + (size_t)slots[l] * 2048;
                for (int i = tid; i < 2048; i += 256) {
                    int row = i >> 4, c = i & 15;
                    *(uint4*)(smem + OFF_W + row * 272 + c * 16) = ph[row * 16 + c];
                    *(uint4*)(smem + OFF_W + 34816 + row * 272 + c * 16) = pl[row * 16 + c];
                }
                __syncthreads();
                wbase = sb + OFF_W;
            }

            float acc[2][8][4];
            #pragma unroll
            for (int i = 0; i < 2; i++)
                #pragma unroll
                for (int j = 0; j < 8; j++)
                    #pragma unroll
                    for (int k = 0; k < 4; k++) acc[i][j][k] = 0.f;

            u32 ab_hi = sb + (u32)(wr * 32 * 272) + a_lo;
            u32 ab_lo = ab_hi + OFF_AL;
            u32 bb_hi = wbase + (u32)(wc * 64 * 272) + b_lo;
            u32 bb_lo = bb_hi + 34816;

            #pragma unroll
            for (int ks = 0; ks < 8; ks++) {
                u32 ah[2][4], alo[2][4];
                #pragma unroll
                for (int rt = 0; rt < 2; rt++) {
                    ldsm4(ab_hi + rt * (16 * 272) + ks * 32,
                          ah[rt][0], ah[rt][1], ah[rt][2], ah[rt][3]);
                    ldsm4(ab_lo + rt * (16 * 272) + ks * 32,
                          alo[rt][0], alo[rt][1], alo[rt][2], alo[rt][3]);
                }
                u32 bh[8][2], bl[8][2];
                #pragma unroll
                for (int np = 0; np < 4; np++) {
                    u32 r0, r1, r2, r3;
                    ldsm4(bb_hi + np * (16 * 272) + ks * 32, r0, r1, r2, r3);
                    bh[np * 2][0] = r0; bh[np * 2][1] = r1;
                    bh[np * 2 + 1][0] = r2; bh[np * 2 + 1][1] = r3;
                    ldsm4(bb_lo + np * (16 * 272) + ks * 32, r0, r1, r2, r3);
                    bl[np * 2][0] = r0; bl[np * 2][1] = r1;
                    bl[np * 2 + 1][0] = r2; bl[np * 2 + 1][1] = r3;
                }
                #pragma unroll
                for (int rt = 0; rt < 2; rt++)
                    #pragma unroll
                    for (int nt = 0; nt < 8; nt++) {
                        mma16816(acc[rt][nt], ah[rt], bh[nt]);
                        mma16816(acc[rt][nt], ah[rt], bl[nt]);
                        mma16816(acc[rt][nt], alo[rt], bh[nt]);
                    }
            }
            __syncthreads();

            if (l < NL - 1) {
                const float* bias = sbias[l];
                #pragma unroll
                for (int rt = 0; rt < 2; rt++) {
                    int r0 = wr * 32 + rt * 16 + gid;
                    #pragma unroll
                    for (int nt = 0; nt < 8; nt++) {
                        int c = wc * 64 + nt * 8 + tig * 2;
                        float b0v = bias[c], b1v = bias[c + 1];
                        float z0 = leaky(acc[rt][nt][0] + b0v);
                        float z1 = leaky(acc[rt][nt][1] + b1v);
                        float z2 = leaky(acc[rt][nt][2] + b0v);
                        float z3 = leaky(acc[rt][nt][3] + b1v);
                        __nv_bfloat16 h0 = __float2bfloat16(z0), h1 = __float2bfloat16(z1);
                        __nv_bfloat16 h2 = __float2bfloat16(z2), h3 = __float2bfloat16(z3);
                        *(u32*)(smem + (size_t)(r0 * 136 + c) * 2) = bfpack(h0, h1);
                        *(u32*)(smem + OFF_AL + (size_t)(r0 * 136 + c) * 2) =
                            bfpack(__float2bfloat16(z0 - __bfloat162float(h0)),
                                   __float2bfloat16(z1 - __bfloat162float(h1)));
                        *(u32*)(smem + (size_t)((r0 + 8) * 136 + c) * 2) = bfpack(h2, h3);
                        *(u32*)(smem + OFF_AL + (size_t)((r0 + 8) * 136 + c) * 2) =
                            bfpack(__float2bfloat16(z2 - __bfloat162float(h2)),
                                   __float2bfloat16(z3 - __bfloat162float(h3)));
                    }
                }
                __syncthreads();
            } else if (EPI == 2) {
                #pragma unroll
                for (int rt = 0; rt < 2; rt++) {
                    int r0 = wr * 32 + rt * 16 + gid;
                    int gr0 = tb + r0, gr1 = gr0 + 8;
                    #pragma unroll
                    for (int nt = 0; nt < 8; nt++) {
                        int c = wc * 64 + nt * 8 + tig * 2;
                        if (gr0 < M)
                            *(float2*)&g_h[(size_t)gr0 * D + c] =
                                make_float2(acc[rt][nt][0], acc[rt][nt][1]);
                        if (gr1 < M)
                            *(float2*)&g_h[(size_t)gr1 * D + c] =
                                make_float2(acc[rt][nt][2], acc[rt][nt][3]);
                    }
                }
                __syncthreads();
            } else {
                const float* bias = sbias[NL - 1];
                #pragma unroll
                for (int rt = 0; rt < 2; rt++) {
                    float s0 = 0.f, q0 = 0.f, s1 = 0.f, q1 = 0.f;
                    #pragma unroll
                    for (int nt = 0; nt < 8; nt++) {
                        int c = wc * 64 + nt * 8 + tig * 2;
                        float b0v = bias[c], b1v = bias[c + 1];
                        float z0 = acc[rt][nt][0] + b0v, z1 = acc[rt][nt][1] + b1v;
                        float z2 = acc[rt][nt][2] + b0v, z3 = acc[rt][nt][3] + b1v;
                        s0 += z0 + z1; q0 += z0 * z0 + z1 * z1;
                        s1 += z2 + z3; q1 += z2 * z2 + z3 * z3;
                    }
                    s0 += __shfl_xor_sync(0xffffffffu, s0, 1);
                    q0 += __shfl_xor_sync(0xffffffffu, q0, 1);
                    s1 += __shfl_xor_sync(0xffffffffu, s1, 1);
                    q1 += __shfl_xor_sync(0xffffffffu, q1, 1);
                    s0 += __shfl_xor_sync(0xffffffffu, s0, 2);
                    q0 += __shfl_xor_sync(0xffffffffu, q0, 2);
                    s1 += __shfl_xor_sync(0xffffffffu, s1, 2);
                    q1 += __shfl_xor_sync(0xffffffffu, q1, 2);
                    int r0 = wr * 32 + rt * 16 + gid;
                    if (tig == 0) {
                        rs[r0 * 2 + wc] = s0; rq[r0 * 2 + wc] = q0;
                        rs[(r0 + 8) * 2 + wc] = s1; rq[(r0 + 8) * 2 + wc] = q1;
                    }
                }
                __syncthreads();
                #pragma unroll
                for (int rt = 0; rt < 2; rt++) {
                    int r0 = wr * 32 + rt * 16 + gid;
                    float S0 = rs[r0 * 2] + rs[r0 * 2 + 1];
                    float Q0 = rq[r0 * 2] + rq[r0 * 2 + 1];
                    float S1 = rs[(r0 + 8) * 2] + rs[(r0 + 8) * 2 + 1];
                    float Q1 = rq[(r0 + 8) * 2] + rq[(r0 + 8) * 2 + 1];
                    float m0 = S0 * (1.f / (float)D);
                    float i0 = rsqrtf(Q0 * (1.f / (float)D) - m0 * m0 + EPSf);
                    float m1 = S1 * (1.f / (float)D);
                    float i1 = rsqrtf(Q1 * (1.f / (float)D) - m1 * m1 + EPSf);
                    int gr0 = tb + r0, gr1 = gr0 + 8;
                    int sidx0 = 0, sidx1 = 0;
                    if (EPI == 1) {
                        if (gr0 < M) sidx0 = esrc[gr0];
                        if (gr1 < M) sidx1 = esrc[gr1];
                    }
                    float ic0 = 0.f, ic1 = 0.f;
                    if (EPI == 3) {
                        if (gr0 < M) ic0 = 1.f / fmaxf(g_cnt[gr0], 1.f);
                        if (gr1 < M) ic1 = 1.f / fmaxf(g_cnt[gr1], 1.f);
                    }
                    #pragma unroll
                    for (int nt = 0; nt < 8; nt++) {
                        int c = wc * 64 + nt * 8 + tig * 2;
                        float b0v = bias[c], b1v = bias[c + 1];
                        float g0 = sg[c], g1 = sg[c + 1];
                        float l0 = sl[c], l1 = sl[c + 1];
                        float o0 = (acc[rt][nt][0] + b0v - m0) * i0 * g0 + l0;
                        float o1 = (acc[rt][nt][1] + b1v - m0) * i0 * g1 + l1;
                        float o2 = (acc[rt][nt][2] + b0v - m1) * i1 * g0 + l0;
                        float o3 = (acc[rt][nt][3] + b1v - m1) * i1 * g1 + l1;
                        if (EPI == 0) {
                            if (gr0 < M) *(float2*)&out[(size_t)gr0 * D + c] = make_float2(o0, o1);
                            if (gr1 < M) *(float2*)&out[(size_t)gr1 * D + c] = make_float2(o2, o3);
                        } else if (EPI == 3) {
                            if (gr0 < M) {
                                float2 ac = *(const float2*)&g_acc[(size_t)gr0 * D + c];
                                *(float2*)&out[(size_t)gr0 * D + c] =
                                    make_float2(o0 + ac.x * ic0, o1 + ac.y * ic0);
                            }
                            if (gr1 < M) {
                                float2 ac = *(const float2*)&g_acc[(size_t)gr1 * D + c];
                                *(float2*)&out[(size_t)gr1 * D + c] =
                                    make_float2(o2 + ac.x * ic1, o3 + ac.y * ic1);
                            }
                        } else {
                            if (gr0 < M) red2(&g_acc[(size_t)sidx0 * D + c], o0, o1);
                            if (gr1 < M) red2(&g_acc[(size_t)sidx1 * D + c], o2, o3);
                        }
                    }
                }
                __syncthreads();
            }
        }
    }
}

// ---------------- host orchestration ----------------
extern "C" void kernel_launch(void* const* d_in, const int* in_sizes, int n_in,
                              void* d_out, int out_size)
{
    const float* node_feat = (const float*)d_in[0];
    const float* edge_feat = (const float*)d_in[1];
    const int*   ei        = (const int*)d_in[2];
    const float* enW1 = (const float*)d_in[3];  const float* enb1 = (const float*)d_in[4];
    const float* enW2 = (const float*)d_in[5];  const float* enb2 = (const float*)d_in[6];
    const float* enW3 = (const float*)d_in[7];  const float* enb3 = (const float*)d_in[8];
    const float* enlg = (const float*)d_in[9];  const float* enlb = (const float*)d_in[10];
    const float* eeW1 = (const float*)d_in[11]; const float* eeb1 = (const float*)d_in[12];
    const float* eeW2 = (const float*)d_in[13]; const float* eeb2 = (const float*)d_in[14];
    const float* eeW3 = (const float*)d_in[15]; const float* eeb3 = (const float*)d_in[16];
    const float* eelg = (const float*)d_in[17]; const float* eelb = (const float*)d_in[18];
    const float* procW = (const float*)d_in[19];
    const float* procb = (const float*)d_in[20];
    const float* bng   = (const float*)d_in[21];
    const float* bnb   = (const float*)d_in[22];
    const float* dW1 = (const float*)d_in[23]; const float* db1 = (const float*)d_in[24];
    const float* dW2 = (const float*)d_in[25]; const float* db2 = (const float*)d_in[26];
    const float* dW3 = (const float*)d_in[27]; const float* db3 = (const float*)d_in[28];
    const float* dlg = (const float*)d_in[29]; const float* dlb = (const float*)d_in[30];
    float* out = (float*)d_out;

    float* hn_ptr = nullptr; cudaGetSymbolAddress((void**)&hn_ptr, g_hn);
    float* y_ptr = nullptr;  cudaGetSymbolAddress((void**)&y_ptr, g_y);

    const int SM_EDGE = 69632 + 2 * 69632 + EDGE_IN * 512 + 6144;   // 217088
    const int SM_NODE = 69632 + 2 * 69632 + NODE_IN * 512 + 6144;   // 224768
    const int SM_CONV = 69632 + 1 * 69632 + 6144;                    // 145408
    const int SM_DEC  = 69632 + 1 * 69632 + 6144;                    // 145408

    cudaFuncSetAttribute(k_fused<EDGE_IN, 2, 1, false>, cudaFuncAttributeMaxDynamicSharedMemorySize, SM_EDGE);
    cudaFuncSetAttribute(k_fused<NODE_IN, 2, 3, false>, cudaFuncAttributeMaxDynamicSharedMemorySize, SM_NODE);
    cudaFuncSetAttribute(k_fused<0, 1, 2, false>, cudaFuncAttributeMaxDynamicSharedMemorySize, SM_CONV);
    cudaFuncSetAttribute(k_fused<0, 1, 2, true>,  cudaFuncAttributeMaxDynamicSharedMemorySize, SM_CONV);
    cudaFuncSetAttribute(k_fused<0, 3, 0, false>, cudaFuncAttributeMaxDynamicSharedMemorySize, SM_DEC);

    int NnT = (Nn + 127) / 128, EeT = Ee / 128;
    int G = 148;

    // 1: weight splits   2: zero   3: count
    k_wsplit_all<<<dim3(64, NSLOT), 256>>>(enW2, enW3, eeW2, eeW3, procW, dW1, dW2, dW3);
    k_zero<<<512, 256>>>();
    k_count<<<(Ee + 255) / 256, 256>>>(ei);
    // 4: edge encoder (profiled) — LN + scatter-sum into g_acc
    k_fused<EDGE_IN, 2, 1, false><<<G, 256, SM_EDGE>>>(
        edge_feat, 2, 3, 0, eeb2, eeb3, nullptr, eeW1, eeb1, eelg, eelb,
        nullptr, ei, Ee, EeT, 0, nullptr, nullptr);
    // 5: node encoder with fused scatter-mean mix -> g_hn
    k_fused<NODE_IN, 2, 3, false><<<G, 256, SM_NODE>>>(
        node_feat, 0, 1, 0, enb2, enb3, nullptr, enW1, enb1, enlg, enlb,
        hn_ptr, nullptr, Nn, NnT, 0, nullptr, nullptr);
    // CSR build
    k_scan<<<1, 1024>>>();
    k_dis<<<(Nn + 255) / 256, 256>>>();
    k_fill<<<(Ee + 255) / 256, 256>>>(ei);

    // processor steps
    for (int s = 0; s < STEPS; s++) {
        const float* b0 = procb + (size_t)(s * 2 + 0) * D;
        const float* b1 = procb + (size_t)(s * 2 + 1) * D;

        k_fused<0, 1, 2, false><<<G, 256, SM_CONV>>>(
            hn_ptr, 4 + 2 * s, 0, 0, nullptr, nullptr, nullptr,
            nullptr, nullptr, nullptr, nullptr, nullptr, nullptr, Nn, NnT,
            0, nullptr, nullptr);
        k_gatherA<<<592, 256>>>(b0, s);
        k_fused<0, 1, 2, true><<<G, 256, SM_CONV>>>(
            y_ptr, 5 + 2 * s, 0, 0, nullptr, nullptr, nullptr,
            nullptr, nullptr, nullptr, nullptr, nullptr, nullptr, Nn, NnT,
            s, bng + (size_t)s * D, bnb + (size_t)s * D);
        k_gatherB<<<592, 256>>>(b1);
    }

    // decoder (3 layers + LN, per-layer W reload)
    k_fused<0, 3, 0, false><<<G, 256, SM_DEC>>>(
        hn_ptr, 14, 15, 16, db1, db2, db3,
        nullptr, nullptr, dlg, dlb, out, nullptr, Nn, NnT, 0, nullptr, nullptr);
}

// round 11
// speedup vs baseline: 1.3590x; 1.0274x over previous
#include <cuda_runtime.h>
#include <cuda_bf16.h>
#include <cstddef>
#include <cstdint>

#define Nn 50000
#define Ee 800000
#define D 128
#define NODE_IN 19
#define EDGE_IN 4
#define STEPS 5
#define EPSf 1e-5f

typedef unsigned long long u64;
typedef unsigned int u32;

// ---------------- device scratch ----------------
__device__ float g_hn[Nn * D];
__device__ float g_acc[Nn * D];
__device__ float g_h[Nn * D];
__device__ float g_y[Nn * D];
__device__ float g_cnt[Nn];
__device__ float g_dis[Nn];
__device__ int   g_degi[Nn];
__device__ int   g_fill[Nn];
__device__ int   g_rowoff[Nn + 1];
__device__ int   g_csrs[Ee];
__device__ float g_csrw[Ee];
__device__ float g_bnsum[STEPS][D];
__device__ float g_bnsq[STEPS][D];

#define NSLOT 17
__device__ __nv_bfloat16 g_whi[NSLOT * D * D];
__device__ __nv_bfloat16 g_wlo[NSLOT * D * D];

__device__ __forceinline__ float leaky(float v) { return v > 0.f ? v : 0.05f * v; }

__device__ __forceinline__ void red4(float* p, float a, float b, float c, float d) {
    asm volatile("red.global.add.v4.f32 [%0], {%1,%2,%3,%4};"
                 :: "l"(p), "f"(a), "f"(b), "f"(c), "f"(d) : "memory");
}
__device__ __forceinline__ void red2(float* p, float a, float b) {
    asm volatile("red.global.add.v2.f32 [%0], {%1,%2};"
                 :: "l"(p), "f"(a), "f"(b) : "memory");
}
__device__ __forceinline__ u32 bfpack(__nv_bfloat16 a, __nv_bfloat16 b) {
    __nv_bfloat162 t = __halves2bfloat162(a, b);
    return *(u32*)&t;
}
__device__ __forceinline__ u32 smem_u32(const void* p) {
    u32 a; asm("{ .reg .u64 t; cvta.to.shared.u64 t, %1; cvt.u32.u64 %0, t; }"
               : "=r"(a) : "l"(p));
    return a;
}
__device__ __forceinline__ void ldsm4(u32 addr, u32& r0, u32& r1, u32& r2, u32& r3) {
    asm volatile("ldmatrix.sync.aligned.m8n8.x4.shared.b16 {%0,%1,%2,%3}, [%4];"
                 : "=r"(r0), "=r"(r1), "=r"(r2), "=r"(r3) : "r"(addr));
}
__device__ __forceinline__ void mma16816(float* c, const u32* a, const u32* b) {
    asm volatile("mma.sync.aligned.m16n8k16.row.col.f32.bf16.bf16.f32 "
                 "{%0,%1,%2,%3}, {%4,%5,%6,%7}, {%8,%9}, {%0,%1,%2,%3};"
                 : "+f"(c[0]), "+f"(c[1]), "+f"(c[2]), "+f"(c[3])
                 : "r"(a[0]), "r"(a[1]), "r"(a[2]), "r"(a[3]), "r"(b[0]), "r"(b[1]));
}

// ---------------- utility kernels ----------------
__global__ void k_zero() {
    int i = blockIdx.x * blockDim.x + threadIdx.x;
    int stride = gridDim.x * blockDim.x;
    for (int j = i; j < Nn * D; j += stride) g_acc[j] = 0.f;
    for (int j = i; j < Nn; j += stride) {
        g_cnt[j] = 0.f; g_degi[j] = 0; g_fill[j] = 0;
    }
    if (i < STEPS * D) { (&g_bnsum[0][0])[i] = 0.f; (&g_bnsq[0][0])[i] = 0.f; }
}

__global__ void k_count(const int* __restrict__ ei) {
    int e = blockIdx.x * blockDim.x + threadIdx.x;
    if (e >= Ee) return;
    atomicAdd(&g_cnt[ei[e]], 1.f);
    atomicAdd(&g_degi[ei[Ee + e]], 1);
}

__global__ void k_scan() {
    __shared__ int ts[1024];
    int t = threadIdx.x;
    const int CH = (Nn + 1023) / 1024;
    int start = t * CH;
    int end = min(start + CH, Nn);
    int sum = 0;
    for (int i = start; i < end; i++) sum += g_degi[i];
    ts[t] = sum;
    __syncthreads();
    for (int off = 1; off < 1024; off <<= 1) {
        int v = (t >= off) ? ts[t - off] : 0;
        __syncthreads();
        ts[t] += v;
        __syncthreads();
    }
    int run = (t == 0) ? 0 : ts[t - 1];
    for (int i = start; i < end; i++) { g_rowoff[i] = run; run += g_degi[i]; }
    if (t == 1023) g_rowoff[Nn] = run;
}

__global__ void k_dis() {
    int i = blockIdx.x * blockDim.x + threadIdx.x;
    if (i < Nn) g_dis[i] = rsqrtf((float)g_degi[i] + 1.0f);
}

__global__ void k_fill(const int* __restrict__ ei) {
    int e = blockIdx.x * blockDim.x + threadIdx.x;
    if (e >= Ee) return;
    int s = ei[e], d = ei[Ee + e];
    int pos = g_rowoff[d] + atomicAdd(&g_fill[d], 1);
    g_csrs[pos] = s;
    g_csrw[pos] = g_dis[s] * g_dis[d];
}

// ---------------- CSR gather kernels (warp per node, 4-edge unroll) ----------------
__device__ __forceinline__ float4 gather_node(int node, int c0) {
    float dd = g_dis[node];
    float d2 = dd * dd;
    float4 a = *(const float4*)&g_h[(size_t)node * D + c0];
    a.x *= d2; a.y *= d2; a.z *= d2; a.w *= d2;
    int p = g_rowoff[node], p1 = g_rowoff[node + 1];
    for (; p + 3 < p1; p += 4) {
        int sA = g_csrs[p];     float wA = g_csrw[p];
        int sB = g_csrs[p + 1]; float wB = g_csrw[p + 1];
        int sC = g_csrs[p + 2]; float wC = g_csrw[p + 2];
        int sD = g_csrs[p + 3]; float wD = g_csrw[p + 3];
        float4 vA = *(const float4*)&g_h[(size_t)sA * D + c0];
        float4 vB = *(const float4*)&g_h[(size_t)sB * D + c0];
        float4 vC = *(const float4*)&g_h[(size_t)sC * D + c0];
        float4 vD = *(const float4*)&g_h[(size_t)sD * D + c0];
        a.x = fmaf(vA.x, wA, a.x); a.y = fmaf(vA.y, wA, a.y);
        a.z = fmaf(vA.z, wA, a.z); a.w = fmaf(vA.w, wA, a.w);
        a.x = fmaf(vB.x, wB, a.x); a.y = fmaf(vB.y, wB, a.y);
        a.z = fmaf(vB.z, wB, a.z); a.w = fmaf(vB.w, wB, a.w);
        a.x = fmaf(vC.x, wC, a.x); a.y = fmaf(vC.y, wC, a.y);
        a.z = fmaf(vC.z, wC, a.z); a.w = fmaf(vC.w, wC, a.w);
        a.x = fmaf(vD.x, wD, a.x); a.y = fmaf(vD.y, wD, a.y);
        a.z = fmaf(vD.z, wD, a.z); a.w = fmaf(vD.w, wD, a.w);
    }
    for (; p < p1; p++) {
        int sA = g_csrs[p]; float wA = g_csrw[p];
        float4 vA = *(const float4*)&g_h[(size_t)sA * D + c0];
        a.x = fmaf(vA.x, wA, a.x); a.y = fmaf(vA.y, wA, a.y);
        a.z = fmaf(vA.z, wA, a.z); a.w = fmaf(vA.w, wA, a.w);
    }
    return a;
}

__global__ void __launch_bounds__(256) k_gatherA(const float* __restrict__ b0, int step) {
    int lane = threadIdx.x & 31;
    int gw = blockIdx.x * 8 + (threadIdx.x >> 5);
    int nw = gridDim.x * 8;
    int c0 = lane * 4;
    float4 bb = *(const float4*)&b0[c0];
    float s0 = 0.f, s1 = 0.f, s2 = 0.f, s3 = 0.f;
    float q0 = 0.f, q1 = 0.f, q2 = 0.f, q3 = 0.f;

    for (int node = gw; node < Nn; node += nw) {
        float4 a = gather_node(node, c0);
        float v0 = leaky(a.x + bb.x), v1 = leaky(a.y + bb.y);
        float v2 = leaky(a.z + bb.z), v3 = leaky(a.w + bb.w);
        *(float4*)&g_y[(size_t)node * D + c0] = make_float4(v0, v1, v2, v3);
        s0 += v0; s1 += v1; s2 += v2; s3 += v3;
        q0 += v0 * v0; q1 += v1 * v1; q2 += v2 * v2; q3 += v3 * v3;
    }
    red4(&g_bnsum[step][c0], s0, s1, s2, s3);
    red4(&g_bnsq[step][c0],  q0, q1, q2, q3);
}

__global__ void __launch_bounds__(256) k_gatherB(const float* __restrict__ b1) {
    int lane = threadIdx.x & 31;
    int gw = blockIdx.x * 8 + (threadIdx.x >> 5);
    int nw = gridDim.x * 8;
    int c0 = lane * 4;
    float4 bb = *(const float4*)&b1[c0];

    for (int node = gw; node < Nn; node += nw) {
        float4 a = gather_node(node, c0);
        float4 h4 = *(const float4*)&g_hn[(size_t)node * D + c0];
        h4.x += a.x + bb.x; h4.y += a.y + bb.y;
        h4.z += a.z + bb.z; h4.w += a.w + bb.w;
        *(float4*)&g_hn[(size_t)node * D + c0] = h4;
    }
}

// all 17 weight splits: grid (64, 17)
__global__ void k_wsplit_all(
    const float* __restrict__ enW2, const float* __restrict__ enW3,
    const float* __restrict__ eeW2, const float* __restrict__ eeW3,
    const float* __restrict__ procW,
    const float* __restrict__ dW1, const float* __restrict__ dW2,
    const float* __restrict__ dW3)
{
    int slot = blockIdx.y;
    const float* W;
    if (slot == 0) W = enW2;
    else if (slot == 1) W = enW3;
    else if (slot == 2) W = eeW2;
    else if (slot == 3) W = eeW3;
    else if (slot < 14) W = procW + (size_t)(slot - 4) * D * D;
    else if (slot == 14) W = dW1;
    else if (slot == 15) W = dW2;
    else W = dW3;
    int i = blockIdx.x * 256 + threadIdx.x;
    int k = i >> 7, n = i & 127;
    float v = W[i];
    __nv_bfloat16 h = __float2bfloat16(v);
    g_whi[slot * D * D + n * D + k] = h;
    g_wlo[slot * D * D + n * D + k] = __float2bfloat16(v - __bfloat162float(h));
}

// ---------------- conv GEMM: 64-row tiles, 2 CTAs/SM ----------------
// smem: A hi [0,17408) | A lo [17408,34816) | W hi [34816,69632) | W lo [69632,104448)
//       | BN consts [104448,105472)
#define CV_AL 17408
#define CV_W  34816
#define CV_C  104448
#define SM_CONV 105472

template <bool BN>
__global__ void __launch_bounds__(256, 2) k_conv(
    const float* __restrict__ in, int slot, int bnstep,
    const float* __restrict__ bng, const float* __restrict__ bnb, int nT)
{
    extern __shared__ char smem[];
    u32 sb = smem_u32(smem);
    int tid = threadIdx.x, lane = tid & 31, wid = tid >> 5;
    int wr = wid & 3, wc = wid >> 2, gid = lane >> 2, tig = lane & 3;

    float* sbns = (float*)(smem + CV_C);
    float* sbnf = (float*)(smem + CV_C + 512);

    if (BN && tid < 128) {
        float m = g_bnsum[bnstep][tid] * (1.f / (float)Nn);
        float v = g_bnsq[bnstep][tid] * (1.f / (float)Nn) - m * m;
        float sc = bng[tid] * rsqrtf(v + EPSf);
        sbns[tid] = sc;
        sbnf[tid] = bnb[tid] - m * sc;
    }
    // load W (hi/lo) once per CTA
    {
        const uint4* ph = ((const uint4*)g_whi) + (size_t)slot * 2048;
        const uint4* pl = ((const uint4*)g_wlo) + (size_t)slot * 2048;
        for (int i = tid; i < 2048; i += 256) {
            int row = i >> 4, c = i & 15;
            *(uint4*)(smem + CV_W + row * 272 + c * 16) = ph[row * 16 + c];
            *(uint4*)(smem + CV_W + 34816 + row * 272 + c * 16) = pl[row * 16 + c];
        }
    }
    __syncthreads();

    u32 a_lo = (u32)((((lane & 7) + ((lane >> 3) & 1) * 8) * 136 + (lane >> 4) * 8) * 2);
    u32 b_lo = (u32)((((lane & 7) + ((lane >> 4) & 1) * 8) * 136 + ((lane >> 3) & 1) * 8) * 2);

    for (int t = blockIdx.x; t < nT; t += gridDim.x) {
        int tb = t * 64;

        // build A tile (64 rows, bf16 hi/lo, optional BN affine)
        for (int idx = tid; idx < 2048; idx += 256) {
            int row = idx >> 5, c4 = idx & 31;
            int gr = min(tb + row, Nn - 1);
            float4 v = ((const float4*)in)[(size_t)gr * 32 + c4];
            if (BN) {
                int c = c4 * 4;
                v.x = fmaf(v.x, sbns[c],     sbnf[c]);
                v.y = fmaf(v.y, sbns[c + 1], sbnf[c + 1]);
                v.z = fmaf(v.z, sbns[c + 2], sbnf[c + 2]);
                v.w = fmaf(v.w, sbns[c + 3], sbnf[c + 3]);
            }
            __nv_bfloat16 h0 = __float2bfloat16(v.x), h1 = __float2bfloat16(v.y);
            __nv_bfloat16 h2 = __float2bfloat16(v.z), h3 = __float2bfloat16(v.w);
            u32 hi01 = bfpack(h0, h1), hi23 = bfpack(h2, h3);
            u32 lo01 = bfpack(__float2bfloat16(v.x - __bfloat162float(h0)),
                              __float2bfloat16(v.y - __bfloat162float(h1)));
            u32 lo23 = bfpack(__float2bfloat16(v.z - __bfloat162float(h2)),
                              __float2bfloat16(v.w - __bfloat162float(h3)));
            *(uint2*)(smem + (size_t)(row * 136 + c4 * 4) * 2) = make_uint2(hi01, hi23);
            *(uint2*)(smem + CV_AL + (size_t)(row * 136 + c4 * 4) * 2) = make_uint2(lo01, lo23);
        }
        __syncthreads();

        float acc[8][4];
        #pragma unroll
        for (int j = 0; j < 8; j++)
            #pragma unroll
            for (int k = 0; k < 4; k++) acc[j][k] = 0.f;

        u32 ab_hi = sb + (u32)(wr * 16 * 272) + a_lo;
        u32 ab_lo = ab_hi + CV_AL;
        u32 bb_hi = sb + CV_W + (u32)(wc * 64 * 272) + b_lo;
        u32 bb_lo = bb_hi + 34816;

        #pragma unroll
        for (int ks = 0; ks < 8; ks++) {
            u32 ah[4], alo[4];
            ldsm4(ab_hi + ks * 32, ah[0], ah[1], ah[2], ah[3]);
            ldsm4(ab_lo + ks * 32, alo[0], alo[1], alo[2], alo[3]);
            u32 bh[8][2], bl[8][2];
            #pragma unroll
            for (int np = 0; np < 4; np++) {
                u32 r0, r1, r2, r3;
                ldsm4(bb_hi + np * (16 * 272) + ks * 32, r0, r1, r2, r3);
                bh[np * 2][0] = r0; bh[np * 2][1] = r1;
                bh[np * 2 + 1][0] = r2; bh[np * 2 + 1][1] = r3;
                ldsm4(bb_lo + np * (16 * 272) + ks * 32, r0, r1, r2, r3);
                bl[np * 2][0] = r0; bl[np * 2][1] = r1;
                bl[np * 2 + 1][0] = r2; bl[np * 2 + 1][1] = r3;
            }
            #pragma unroll
            for (int nt = 0; nt < 8; nt++) {
                mma16816(acc[nt], ah, bh[nt]);
                mma16816(acc[nt], ah, bl[nt]);
                mma16816(acc[nt], alo, bh[nt]);
            }
        }
        __syncthreads();

        int r0 = wr * 16 + gid;
        int gr0 = tb + r0, gr1 = gr0 + 8;
        #pragma unroll
        for (int nt = 0; nt < 8; nt++) {
            int c = wc * 64 + nt * 8 + tig * 2;
            if (gr0 < Nn)
                *(float2*)&g_h[(size_t)gr0 * D + c] = make_float2(acc[nt][0], acc[nt][1]);
            if (gr1 < Nn)
                *(float2*)&g_h[(size_t)gr1 * D + c] = make_float2(acc[nt][2], acc[nt][3]);
        }
        __syncthreads();
    }
}

// ---------------- persistent fused MLP kernel (raw mma, R7 geometry) ----------------
// 8 warps, grid 4x2: warp = 32 rows x 64 cols. A/W 128x128 bf16, stride 136 elems.
// EPI: 0 = LN -> out; 1 = LN -> red2 scatter g_acc[esrc];
//      3 = LN + scatter-mean mix -> out (node encoder)
template <int KIN, int NL, int EPI>
__global__ void __launch_bounds__(256, 1) k_fused(
    const float* __restrict__ in,
    int slot0, int slot1, int slot2,
    const float* __restrict__ wb0, const float* __restrict__ wb1, const float* __restrict__ wb2,
    const float* __restrict__ W1, const float* __restrict__ bias1,
    const float* __restrict__ lng, const float* __restrict__ lnb,
    float* __restrict__ out, const int* __restrict__ esrc, int M, int nT)
{
    constexpr bool PRE = (NL <= 2);
    constexpr int NW = PRE ? NL : 1;
    constexpr int OFF_AL = 34816;
    constexpr int OFF_W = 69632;
    constexpr int OFF_W1S = OFF_W + NW * 69632;
    constexpr int OFF_C = OFF_W1S + (KIN > 0 ? KIN * 512 : 0);
    extern __shared__ char smem[];
    u32 sb = smem_u32(smem);

    int tid = threadIdx.x, lane = tid & 31, wid = tid >> 5;
    int wr = wid & 3, wc = wid >> 2, gid = lane >> 2, tig = lane & 3;

    float* sbias0 = (float*)(smem + OFF_C);
    float* sbias1 = (float*)(smem + OFF_C + 512);
    float* sbias2 = (float*)(smem + OFF_C + 1024);
    float* sg  = (float*)(smem + OFF_C + 1536);
    float* sl  = (float*)(smem + OFF_C + 2048);
    float* sb1 = (float*)(smem + OFF_C + 2560);
    float* rs  = (float*)(smem + OFF_C + 3072);   // [128][2]
    float* rq  = (float*)(smem + OFF_C + 4096);   // [128][2]
    float* sbias[3] = {sbias0, sbias1, sbias2};

    int slots[3] = {slot0, slot1, slot2};
    const float* wbs[3] = {wb0, wb1, wb2};

    if (tid < 128) {
        #pragma unroll
        for (int l = 0; l < NL; l++) sbias[l][tid] = wbs[l][tid];
        sg[tid] = lng[tid]; sl[tid] = lnb[tid];
        if (KIN > 0) sb1[tid] = bias1[tid];
    }
    if (KIN > 0) {
        float* W1s = (float*)(smem + OFF_W1S);
        for (int i = tid; i < KIN * 128; i += 256) W1s[i] = W1[i];
    }
    if (PRE) {
        #pragma unroll
        for (int l = 0; l < NL; l++) {
            const uint4* ph = ((const uint4*)g_whi) + (size_t)slots[l] * 2048;
            const uint4* pl = ((const uint4*)g_wlo) + (size_t)slots[l] * 2048;
            char* dh = smem + OFF_W + l * 69632;
            for (int i = tid; i < 2048; i += 256) {
                int row = i >> 4, c = i & 15;
                *(uint4*)(dh + row * 272 + c * 16) = ph[row * 16 + c];
                *(uint4*)(dh + 34816 + row * 272 + c * 16) = pl[row * 16 + c];
            }
        }
    }
    __syncthreads();

    u32 a_lo = (u32)((((lane & 7) + ((lane >> 3) & 1) * 8) * 136 + (lane >> 4) * 8) * 2);
    u32 b_lo = (u32)((((lane & 7) + ((lane >> 4) & 1) * 8) * 136 + ((lane >> 3) & 1) * 8) * 2);

    for (int t = blockIdx.x; t < nT; t += gridDim.x) {
        int tb = t * 128;

        // ---- build A tile (bf16 hi/lo) ----
        if (KIN > 0) {
            float* W1s = (float*)(smem + OFF_W1S);
            int r = tid >> 1, half = tid & 1;
            int gr = min(tb + r, M - 1);
            float xv[KIN > 0 ? KIN : 1];
            #pragma unroll
            for (int k = 0; k < KIN; k++) xv[k] = in[(size_t)gr * KIN + k];
            #pragma unroll
            for (int c4 = 0; c4 < 4; c4++) {
                int cbase = half * 64 + c4 * 16;
                float a16[16];
                #pragma unroll
                for (int j = 0; j < 16; j++) a16[j] = sb1[cbase + j];
                #pragma unroll
                for (int k = 0; k < KIN; k++) {
                    float x = xv[k];
                    const float* wrow = &W1s[k * 128 + cbase];
                    #pragma unroll
                    for (int j = 0; j < 16; j++) a16[j] = fmaf(x, wrow[j], a16[j]);
                }
                #pragma unroll
                for (int j = 0; j < 16; j += 2) {
                    float z0 = leaky(a16[j]), z1 = leaky(a16[j + 1]);
                    __nv_bfloat16 h0 = __float2bfloat16(z0), h1 = __float2bfloat16(z1);
                    *(u32*)(smem + (size_t)(r * 136 + cbase + j) * 2) = bfpack(h0, h1);
                    *(u32*)(smem + OFF_AL + (size_t)(r * 136 + cbase + j) * 2) =
                        bfpack(__float2bfloat16(z0 - __bfloat162float(h0)),
                               __float2bfloat16(z1 - __bfloat162float(h1)));
                }
            }
        } else {
            for (int idx = tid; idx < 4096; idx += 256) {
                int row = idx >> 5, c4 = idx & 31;
                int gr = min(tb + row, M - 1);
                float4 v = ((const float4*)in)[(size_t)gr * 32 + c4];
                __nv_bfloat16 h0 = __float2bfloat16(v.x), h1 = __float2bfloat16(v.y);
                __nv_bfloat16 h2 = __float2bfloat16(v.z), h3 = __float2bfloat16(v.w);
                u32 hi01 = bfpack(h0, h1), hi23 = bfpack(h2, h3);
                u32 lo01 = bfpack(__float2bfloat16(v.x - __bfloat162float(h0)),
                                  __float2bfloat16(v.y - __bfloat162float(h1)));
                u32 lo23 = bfpack(__float2bfloat16(v.z - __bfloat162float(h2)),
                                  __float2bfloat16(v.w - __bfloat162float(h3)));
                *(uint2*)(smem + (size_t)(row * 136 + c4 * 4) * 2) = make_uint2(hi01, hi23);
                *(uint2*)(smem + OFF_AL + (size_t)(row * 136 + c4 * 4) * 2) = make_uint2(lo01, lo23);
            }
        }
        __syncthreads();

        // ---- layers ----
        #pragma unroll
        for (int l = 0; l < NL; l++) {
            u32 wbase;
            if (PRE) {
                wbase = sb + OFF_W + l * 69632;
            } else {
                const uint4* ph = ((const uint4*)g_whi) + (size_t)slots[l] * 2048;
                const uint4* pl = ((const uint4*)g_wlo) + (size_t)slots[l] * 2048;
                for (int i = tid; i < 2048; i += 256) {
                    int row = i >> 4, c = i & 15;
                    *(uint4*)(smem + OFF_W + row * 272 + c * 16) = ph[row * 16 + c];
                    *(uint4*)(smem + OFF_W + 34816 + row * 272 + c * 16) = pl[row * 16 + c];
                }
                __syncthreads();
                wbase = sb + OFF_W;
            }

            float acc[2][8][4];
            #pragma unroll
            for (int i = 0; i < 2; i++)
                #pragma unroll
                for (int j = 0; j < 8; j++)
                    #pragma unroll
                    for (int k = 0; k < 4; k++) acc[i][j][k] = 0.f;

            u32 ab_hi = sb + (u32)(wr * 32 * 272) + a_lo;
            u32 ab_lo = ab_hi + OFF_AL;
            u32 bb_hi = wbase + (u32)(wc * 64 * 272) + b_lo;
            u32 bb_lo = bb_hi + 34816;

            #pragma unroll
            for (int ks = 0; ks < 8; ks++) {
                u32 ah[2][4], alo[2][4];
                #pragma unroll
                for (int rt = 0; rt < 2; rt++) {
                    ldsm4(ab_hi + rt * (16 * 272) + ks * 32,
                          ah[rt][0], ah[rt][1], ah[rt][2], ah[rt][3]);
                    ldsm4(ab_lo + rt * (16 * 272) + ks * 32,
                          alo[rt][0], alo[rt][1], alo[rt][2], alo[rt][3]);
                }
                u32 bh[8][2], bl[8][2];
                #pragma unroll
                for (int np = 0; np < 4; np++) {
                    u32 r0, r1, r2, r3;
                    ldsm4(bb_hi + np * (16 * 272) + ks * 32, r0, r1, r2, r3);
                    bh[np * 2][0] = r0; bh[np * 2][1] = r1;
                    bh[np * 2 + 1][0] = r2; bh[np * 2 + 1][1] = r3;
                    ldsm4(bb_lo + np * (16 * 272) + ks * 32, r0, r1, r2, r3);
                    bl[np * 2][0] = r0; bl[np * 2][1] = r1;
                    bl[np * 2 + 1][0] = r2; bl[np * 2 + 1][1] = r3;
                }
                #pragma unroll
                for (int rt = 0; rt < 2; rt++)
                    #pragma unroll
                    for (int nt = 0; nt < 8; nt++) {
                        mma16816(acc[rt][nt], ah[rt], bh[nt]);
                        mma16816(acc[rt][nt], ah[rt], bl[nt]);
                        mma16816(acc[rt][nt], alo[rt], bh[nt]);
                    }
            }
            __syncthreads();

            if (l < NL - 1) {
                const float* bias = sbias[l];
                #pragma unroll
                for (int rt = 0; rt < 2; rt++) {
                    int r0 = wr * 32 + rt * 16 + gid;
                    #pragma unroll
                    for (int nt = 0; nt < 8; nt++) {
                        int c = wc * 64 + nt * 8 + tig * 2;
                        float b0v = bias[c], b1v = bias[c + 1];
                        float z0 = leaky(acc[rt][nt][0] + b0v);
                        float z1 = leaky(acc[rt][nt][1] + b1v);
                        float z2 = leaky(acc[rt][nt][2] + b0v);
                        float z3 = leaky(acc[rt][nt][3] + b1v);
                        __nv_bfloat16 h0 = __float2bfloat16(z0), h1 = __float2bfloat16(z1);
                        __nv_bfloat16 h2 = __float2bfloat16(z2), h3 = __float2bfloat16(z3);
                        *(u32*)(smem + (size_t)(r0 * 136 + c) * 2) = bfpack(h0, h1);
                        *(u32*)(smem + OFF_AL + (size_t)(r0 * 136 + c) * 2) =
                            bfpack(__float2bfloat16(z0 - __bfloat162float(h0)),
                                   __float2bfloat16(z1 - __bfloat162float(h1)));
                        *(u32*)(smem + (size_t)((r0 + 8) * 136 + c) * 2) = bfpack(h2, h3);
                        *(u32*)(smem + OFF_AL + (size_t)((r0 + 8) * 136 + c) * 2) =
                            bfpack(__float2bfloat16(z2 - __bfloat162float(h2)),
                                   __float2bfloat16(z3 - __bfloat162float(h3)));
                    }
                }
                __syncthreads();
            } else {
                const float* bias = sbias[NL - 1];
                #pragma unroll
                for (int rt = 0; rt < 2; rt++) {
                    float s0 = 0.f, q0 = 0.f, s1 = 0.f, q1 = 0.f;
                    #pragma unroll
                    for (int nt = 0; nt < 8; nt++) {
                        int c = wc * 64 + nt * 8 + tig * 2;
                        float b0v = bias[c], b1v = bias[c + 1];
                        float z0 = acc[rt][nt][0] + b0v, z1 = acc[rt][nt][1] + b1v;
                        float z2 = acc[rt][nt][2] + b0v, z3 = acc[rt][nt][3] + b1v;
                        s0 += z0 + z1; q0 += z0 * z0 + z1 * z1;
                        s1 += z2 + z3; q1 += z2 * z2 + z3 * z3;
                    }
                    s0 += __shfl_xor_sync(0xffffffffu, s0, 1);
                    q0 += __shfl_xor_sync(0xffffffffu, q0, 1);
                    s1 += __shfl_xor_sync(0xffffffffu, s1, 1);
                    q1 += __shfl_xor_sync(0xffffffffu, q1, 1);
                    s0 += __shfl_xor_sync(0xffffffffu, s0, 2);
                    q0 += __shfl_xor_sync(0xffffffffu, q0, 2);
                    s1 += __shfl_xor_sync(0xffffffffu, s1, 2);
                    q1 += __shfl_xor_sync(0xffffffffu, q1, 2);
                    int r0 = wr * 32 + rt * 16 + gid;
                    if (tig == 0) {
                        rs[r0 * 2 + wc] = s0; rq[r0 * 2 + wc] = q0;
                        rs[(r0 + 8) * 2 + wc] = s1; rq[(r0 + 8) * 2 + wc] = q1;
                    }
                }
                __syncthreads();
                #pragma unroll
                for (int rt = 0; rt < 2; rt++) {
                    int r0 = wr * 32 + rt * 16 + gid;
                    float S0 = rs[r0 * 2] + rs[r0 * 2 + 1];
                    float Q0 = rq[r0 * 2] + rq[r0 * 2 + 1];
                    float S1 = rs[(r0 + 8) * 2] + rs[(r0 + 8) * 2 + 1];
                    float Q1 = rq[(r0 + 8) * 2] + rq[(r0 + 8) * 2 + 1];
                    float m0 = S0 * (1.f / (float)D);
                    float i0 = rsqrtf(Q0 * (1.f / (float)D) - m0 * m0 + EPSf);
                    float m1 = S1 * (1.f / (float)D);
                    float i1 = rsqrtf(Q1 * (1.f / (float)D) - m1 * m1 + EPSf);
                    int gr0 = tb + r0, gr1 = gr0 + 8;
                    int sidx0 = 0, sidx1 = 0;
                    if (EPI == 1) {
                        if (gr0 < M) sidx0 = esrc[gr0];
                        if (gr1 < M) sidx1 = esrc[gr1];
                    }
                    float ic0 = 0.f, ic1 = 0.f;
                    if (EPI == 3) {
                        if (gr0 < M) ic0 = 1.f / fmaxf(g_cnt[gr0], 1.f);
                        if (gr1 < M) ic1 = 1.f / fmaxf(g_cnt[gr1], 1.f);
                    }
                    #pragma unroll
                    for (int nt = 0; nt < 8; nt++) {
                        int c = wc * 64 + nt * 8 + tig * 2;
                        float b0v = bias[c], b1v = bias[c + 1];
                        float g0 = sg[c], g1 = sg[c + 1];
                        float l0 = sl[c], l1 = sl[c + 1];
                        float o0 = (acc[rt][nt][0] + b0v - m0) * i0 * g0 + l0;
                        float o1 = (acc[rt][nt][1] + b1v - m0) * i0 * g1 + l1;
                        float o2 = (acc[rt][nt][2] + b0v - m1) * i1 * g0 + l0;
                        float o3 = (acc[rt][nt][3] + b1v - m1) * i1 * g1 + l1;
                        if (EPI == 0) {
                            if (gr0 < M) *(float2*)&out[(size_t)gr0 * D + c] = make_float2(o0, o1);
                            if (gr1 < M) *(float2*)&out[(size_t)gr1 * D + c] = make_float2(o2, o3);
                        } else if (EPI == 3) {
                            if (gr0 < M) {
                                float2 ac = *(const float2*)&g_acc[(size_t)gr0 * D + c];
                                *(float2*)&out[(size_t)gr0 * D + c] =
                                    make_float2(o0 + ac.x * ic0, o1 + ac.y * ic0);
                            }
                            if (gr1 < M) {
                                float2 ac = *(const float2*)&g_acc[(size_t)gr1 * D + c];
                                *(float2*)&out[(size_t)gr1 * D + c] =
                                    make_float2(o2 + ac.x * ic1, o3 + ac.y * ic1);
                            }
                        } else {
                            if (gr0 < M) red2(&g_acc[(size_t)sidx0 * D + c], o0, o1);
                            if (gr1 < M) red2(&g_acc[(size_t)sidx1 * D + c], o2, o3);
                        }
                    }
                }
                __syncthreads();
            }
        }
    }
}

// ---------------- host orchestration ----------------
extern "C" void kernel_launch(void* const* d_in, const int* in_sizes, int n_in,
                              void* d_out, int out_size)
{
    const float* node_feat = (const float*)d_in[0];
    const float* edge_feat = (const float*)d_in[1];
    const int*   ei        = (const int*)d_in[2];
    const float* enW1 = (const float*)d_in[3];  const float* enb1 = (const float*)d_in[4];
    const float* enW2 = (const float*)d_in[5];  const float* enb2 = (const float*)d_in[6];
    const float* enW3 = (const float*)d_in[7];  const float* enb3 = (const float*)d_in[8];
    const float* enlg = (const float*)d_in[9];  const float* enlb = (const float*)d_in[10];
    const float* eeW1 = (const float*)d_in[11]; const float* eeb1 = (const float*)d_in[12];
    const float* eeW2 = (const float*)d_in[13]; const float* eeb2 = (const float*)d_in[14];
    const float* eeW3 = (const float*)d_in[15]; const float* eeb3 = (const float*)d_in[16];
    const float* eelg = (const float*)d_in[17]; const float* eelb = (const float*)d_in[18];
    const float* procW = (const float*)d_in[19];
    const float* procb = (const float*)d_in[20];
    const float* bng   = (const float*)d_in[21];
    const float* bnb   = (const float*)d_in[22];
    const float* dW1 = (const float*)d_in[23]; const float* db1 = (const float*)d_in[24];
    const float* dW2 = (const float*)d_in[25]; const float* db2 = (const float*)d_in[26];
    const float* dW3 = (const float*)d_in[27]; const float* db3 = (const float*)d_in[28];
    const float* dlg = (const float*)d_in[29]; const float* dlb = (const float*)d_in[30];
    float* out = (float*)d_out;

    float* hn_ptr = nullptr; cudaGetSymbolAddress((void**)&hn_ptr, g_hn);
    float* y_ptr = nullptr;  cudaGetSymbolAddress((void**)&y_ptr, g_y);

    const int SM_EDGE = 69632 + 2 * 69632 + EDGE_IN * 512 + 5120;   // 216064
    const int SM_NODE = 69632 + 2 * 69632 + NODE_IN * 512 + 5120;   // 223744
    const int SM_DEC  = 69632 + 1 * 69632 + 5120;                    // 144384

    cudaFuncSetAttribute(k_fused<EDGE_IN, 2, 1>, cudaFuncAttributeMaxDynamicSharedMemorySize, SM_EDGE);
    cudaFuncSetAttribute(k_fused<NODE_IN, 2, 3>, cudaFuncAttributeMaxDynamicSharedMemorySize, SM_NODE);
    cudaFuncSetAttribute(k_fused<0, 3, 0>, cudaFuncAttributeMaxDynamicSharedMemorySize, SM_DEC);
    cudaFuncSetAttribute(k_conv<false>, cudaFuncAttributeMaxDynamicSharedMemorySize, SM_CONV);
    cudaFuncSetAttribute(k_conv<true>,  cudaFuncAttributeMaxDynamicSharedMemorySize, SM_CONV);

    int NnT = (Nn + 127) / 128, EeT = Ee / 128;
    int NnT64 = (Nn + 63) / 64;
    int G = 148, G2 = 296;

    // 1: weight splits   2: zero   3: count
    k_wsplit_all<<<dim3(64, NSLOT), 256>>>(enW2, enW3, eeW2, eeW3, procW, dW1, dW2, dW3);
    k_zero<<<512, 256>>>();
    k_count<<<(Ee + 255) / 256, 256>>>(ei);
    // 4: edge encoder (profiled) — LN + scatter-sum into g_acc
    k_fused<EDGE_IN, 2, 1><<<G, 256, SM_EDGE>>>(
        edge_feat, 2, 3, 0, eeb2, eeb3, nullptr, eeW1, eeb1, eelg, eelb,
        nullptr, ei, Ee, EeT);
    // 5: node encoder with fused scatter-mean mix -> g_hn
    k_fused<NODE_IN, 2, 3><<<G, 256, SM_NODE>>>(
        node_feat, 0, 1, 0, enb2, enb3, nullptr, enW1, enb1, enlg, enlb,
        hn_ptr, nullptr, Nn, NnT);
    // CSR build
    k_scan<<<1, 1024>>>();
    k_dis<<<(Nn + 255) / 256, 256>>>();
    k_fill<<<(Ee + 255) / 256, 256>>>(ei);

    // processor steps
    for (int s = 0; s < STEPS; s++) {
        const float* b0 = procb + (size_t)(s * 2 + 0) * D;
        const float* b1 = procb + (size_t)(s * 2 + 1) * D;

        k_conv<false><<<G2, 256, SM_CONV>>>(hn_ptr, 4 + 2 * s, 0, nullptr, nullptr, NnT64);
        k_gatherA<<<592, 256>>>(b0, s);
        k_conv<true><<<G2, 256, SM_CONV>>>(y_ptr, 5 + 2 * s, s,
                                           bng + (size_t)s * D, bnb + (size_t)s * D, NnT64);
        k_gatherB<<<592, 256>>>(b1);
    }

    // decoder (3 layers + LN, per-layer W reload)
    k_fused<0, 3, 0><<<G, 256, SM_DEC>>>(
        hn_ptr, 14, 15, 16, db1, db2, db3,
        nullptr, nullptr, dlg, dlb, out, nullptr, Nn, NnT);
}

// round 12
// speedup vs baseline: 1.3830x; 1.0176x over previous
#include <cuda_runtime.h>
#include <cuda_bf16.h>
#include <cuda_fp16.h>
#include <cstddef>
#include <cstdint>

#define Nn 50000
#define Ee 800000
#define D 128
#define NODE_IN 19
#define EDGE_IN 4
#define STEPS 5
#define EPSf 1e-5f

typedef unsigned long long u64;
typedef unsigned int u32;

// ---------------- device scratch ----------------
__device__ float g_hn[Nn * D];
__device__ float g_acc[Nn * D];
__device__ __half g_h16[Nn * D];   // conv output, fp16 (gather-only consumer)
__device__ float g_y[Nn * D];
__device__ float g_cnt[Nn];
__device__ float g_dis[Nn];
__device__ int   g_degi[Nn];
__device__ int   g_fill[Nn];
__device__ int   g_rowoff[Nn + 1];
__device__ int   g_csrs[Ee];
__device__ float g_csrw[Ee];
__device__ float g_bnsum[STEPS][D];
__device__ float g_bnsq[STEPS][D];

#define NSLOT 17
__device__ __nv_bfloat16 g_whi[NSLOT * D * D];
__device__ __nv_bfloat16 g_wlo[NSLOT * D * D];

__device__ __forceinline__ float leaky(float v) { return v > 0.f ? v : 0.05f * v; }

__device__ __forceinline__ void red4(float* p, float a, float b, float c, float d) {
    asm volatile("red.global.add.v4.f32 [%0], {%1,%2,%3,%4};"
                 :: "l"(p), "f"(a), "f"(b), "f"(c), "f"(d) : "memory");
}
__device__ __forceinline__ void red2(float* p, float a, float b) {
    asm volatile("red.global.add.v2.f32 [%0], {%1,%2};"
                 :: "l"(p), "f"(a), "f"(b) : "memory");
}
__device__ __forceinline__ u32 bfpack(__nv_bfloat16 a, __nv_bfloat16 b) {
    __nv_bfloat162 t = __halves2bfloat162(a, b);
    return *(u32*)&t;
}
__device__ __forceinline__ u32 smem_u32(const void* p) {
    u32 a; asm("{ .reg .u64 t; cvta.to.shared.u64 t, %1; cvt.u32.u64 %0, t; }"
               : "=r"(a) : "l"(p));
    return a;
}
__device__ __forceinline__ void ldsm4(u32 addr, u32& r0, u32& r1, u32& r2, u32& r3) {
    asm volatile("ldmatrix.sync.aligned.m8n8.x4.shared.b16 {%0,%1,%2,%3}, [%4];"
                 : "=r"(r0), "=r"(r1), "=r"(r2), "=r"(r3) : "r"(addr));
}
__device__ __forceinline__ void mma16816(float* c, const u32* a, const u32* b) {
    asm volatile("mma.sync.aligned.m16n8k16.row.col.f32.bf16.bf16.f32 "
                 "{%0,%1,%2,%3}, {%4,%5,%6,%7}, {%8,%9}, {%0,%1,%2,%3};"
                 : "+f"(c[0]), "+f"(c[1]), "+f"(c[2]), "+f"(c[3])
                 : "r"(a[0]), "r"(a[1]), "r"(a[2]), "r"(a[3]), "r"(b[0]), "r"(b[1]));
}

// fp16 row load: 4 channels (8 bytes) -> float4
__device__ __forceinline__ float4 h16_load(int row, int c0) {
    uint2 raw = *(const uint2*)&g_h16[(size_t)row * D + c0];
    __half2 p0 = *(__half2*)&raw.x;
    __half2 p1 = *(__half2*)&raw.y;
    float2 f0 = __half22float2(p0);
    float2 f1 = __half22float2(p1);
    return make_float4(f0.x, f0.y, f1.x, f1.y);
}

// ---------------- utility kernels ----------------
__global__ void k_zero() {
    int i = blockIdx.x * blockDim.x + threadIdx.x;
    int stride = gridDim.x * blockDim.x;
    for (int j = i; j < Nn * D; j += stride) g_acc[j] = 0.f;
    for (int j = i; j < Nn; j += stride) {
        g_cnt[j] = 0.f; g_degi[j] = 0; g_fill[j] = 0;
    }
    if (i < STEPS * D) { (&g_bnsum[0][0])[i] = 0.f; (&g_bnsq[0][0])[i] = 0.f; }
}

__global__ void k_count(const int* __restrict__ ei) {
    int e = blockIdx.x * blockDim.x + threadIdx.x;
    if (e >= Ee) return;
    atomicAdd(&g_cnt[ei[e]], 1.f);
    atomicAdd(&g_degi[ei[Ee + e]], 1);
}

__global__ void k_scan() {
    __shared__ int ts[1024];
    int t = threadIdx.x;
    const int CH = (Nn + 1023) / 1024;
    int start = t * CH;
    int end = min(start + CH, Nn);
    int sum = 0;
    for (int i = start; i < end; i++) sum += g_degi[i];
    ts[t] = sum;
    __syncthreads();
    for (int off = 1; off < 1024; off <<= 1) {
        int v = (t >= off) ? ts[t - off] : 0;
        __syncthreads();
        ts[t] += v;
        __syncthreads();
    }
    int run = (t == 0) ? 0 : ts[t - 1];
    for (int i = start; i < end; i++) { g_rowoff[i] = run; run += g_degi[i]; }
    if (t == 1023) g_rowoff[Nn] = run;
}

__global__ void k_dis() {
    int i = blockIdx.x * blockDim.x + threadIdx.x;
    if (i < Nn) g_dis[i] = rsqrtf((float)g_degi[i] + 1.0f);
}

__global__ void k_fill(const int* __restrict__ ei) {
    int e = blockIdx.x * blockDim.x + threadIdx.x;
    if (e >= Ee) return;
    int s = ei[e], d = ei[Ee + e];
    int pos = g_rowoff[d] + atomicAdd(&g_fill[d], 1);
    g_csrs[pos] = s;
    g_csrw[pos] = g_dis[s] * g_dis[d];
}

// ---------------- CSR gather kernels (warp per node, 4-edge unroll, fp16 h) ----------------
__device__ __forceinline__ float4 gather_node(int node, int c0) {
    float dd = g_dis[node];
    float d2 = dd * dd;
    float4 a = h16_load(node, c0);
    a.x *= d2; a.y *= d2; a.z *= d2; a.w *= d2;
    int p = g_rowoff[node], p1 = g_rowoff[node + 1];
    for (; p + 3 < p1; p += 4) {
        int sA = g_csrs[p];     float wA = g_csrw[p];
        int sB = g_csrs[p + 1]; float wB = g_csrw[p + 1];
        int sC = g_csrs[p + 2]; float wC = g_csrw[p + 2];
        int sD = g_csrs[p + 3]; float wD = g_csrw[p + 3];
        float4 vA = h16_load(sA, c0);
        float4 vB = h16_load(sB, c0);
        float4 vC = h16_load(sC, c0);
        float4 vD = h16_load(sD, c0);
        a.x = fmaf(vA.x, wA, a.x); a.y = fmaf(vA.y, wA, a.y);
        a.z = fmaf(vA.z, wA, a.z); a.w = fmaf(vA.w, wA, a.w);
        a.x = fmaf(vB.x, wB, a.x); a.y = fmaf(vB.y, wB, a.y);
        a.z = fmaf(vB.z, wB, a.z); a.w = fmaf(vB.w, wB, a.w);
        a.x = fmaf(vC.x, wC, a.x); a.y = fmaf(vC.y, wC, a.y);
        a.z = fmaf(vC.z, wC, a.z); a.w = fmaf(vC.w, wC, a.w);
        a.x = fmaf(vD.x, wD, a.x); a.y = fmaf(vD.y, wD, a.y);
        a.z = fmaf(vD.z, wD, a.z); a.w = fmaf(vD.w, wD, a.w);
    }
    for (; p < p1; p++) {
        int sA = g_csrs[p]; float wA = g_csrw[p];
        float4 vA = h16_load(sA, c0);
        a.x = fmaf(vA.x, wA, a.x); a.y = fmaf(vA.y, wA, a.y);
        a.z = fmaf(vA.z, wA, a.z); a.w = fmaf(vA.w, wA, a.w);
    }
    return a;
}

__global__ void __launch_bounds__(256) k_gatherA(const float* __restrict__ b0, int step) {
    int lane = threadIdx.x & 31;
    int gw = blockIdx.x * 8 + (threadIdx.x >> 5);
    int nw = gridDim.x * 8;
    int c0 = lane * 4;
    float4 bb = *(const float4*)&b0[c0];
    float s0 = 0.f, s1 = 0.f, s2 = 0.f, s3 = 0.f;
    float q0 = 0.f, q1 = 0.f, q2 = 0.f, q3 = 0.f;

    for (int node = gw; node < Nn; node += nw) {
        float4 a = gather_node(node, c0);
        float v0 = leaky(a.x + bb.x), v1 = leaky(a.y + bb.y);
        float v2 = leaky(a.z + bb.z), v3 = leaky(a.w + bb.w);
        *(float4*)&g_y[(size_t)node * D + c0] = make_float4(v0, v1, v2, v3);
        s0 += v0; s1 += v1; s2 += v2; s3 += v3;
        q0 += v0 * v0; q1 += v1 * v1; q2 += v2 * v2; q3 += v3 * v3;
    }
    red4(&g_bnsum[step][c0], s0, s1, s2, s3);
    red4(&g_bnsq[step][c0],  q0, q1, q2, q3);
}

__global__ void __launch_bounds__(256) k_gatherB(const float* __restrict__ b1) {
    int lane = threadIdx.x & 31;
    int gw = blockIdx.x * 8 + (threadIdx.x >> 5);
    int nw = gridDim.x * 8;
    int c0 = lane * 4;
    float4 bb = *(const float4*)&b1[c0];

    for (int node = gw; node < Nn; node += nw) {
        float4 a = gather_node(node, c0);
        float4 h4 = *(const float4*)&g_hn[(size_t)node * D + c0];
        h4.x += a.x + bb.x; h4.y += a.y + bb.y;
        h4.z += a.z + bb.z; h4.w += a.w + bb.w;
        *(float4*)&g_hn[(size_t)node * D + c0] = h4;
    }
}

// all 17 weight splits: grid (64, 17)
__global__ void k_wsplit_all(
    const float* __restrict__ enW2, const float* __restrict__ enW3,
    const float* __restrict__ eeW2, const float* __restrict__ eeW3,
    const float* __restrict__ procW,
    const float* __restrict__ dW1, const float* __restrict__ dW2,
    const float* __restrict__ dW3)
{
    int slot = blockIdx.y;
    const float* W;
    if (slot == 0) W = enW2;
    else if (slot == 1) W = enW3;
    else if (slot == 2) W = eeW2;
    else if (slot == 3) W = eeW3;
    else if (slot < 14) W = procW + (size_t)(slot - 4) * D * D;
    else if (slot == 14) W = dW1;
    else if (slot == 15) W = dW2;
    else W = dW3;
    int i = blockIdx.x * 256 + threadIdx.x;
    int k = i >> 7, n = i & 127;
    float v = W[i];
    __nv_bfloat16 h = __float2bfloat16(v);
    g_whi[slot * D * D + n * D + k] = h;
    g_wlo[slot * D * D + n * D + k] = __float2bfloat16(v - __bfloat162float(h));
}

// ---------------- conv GEMM: 64-row tiles, 2 CTAs/SM, fp16 output ----------------
#define CV_AL 17408
#define CV_W  34816
#define CV_C  104448
#define SM_CONV 105472

template <bool BN>
__global__ void __launch_bounds__(256, 2) k_conv(
    const float* __restrict__ in, int slot, int bnstep,
    const float* __restrict__ bng, const float* __restrict__ bnb, int nT)
{
    extern __shared__ char smem[];
    u32 sb = smem_u32(smem);
    int tid = threadIdx.x, lane = tid & 31, wid = tid >> 5;
    int wr = wid & 3, wc = wid >> 2, gid = lane >> 2, tig = lane & 3;

    float* sbns = (float*)(smem + CV_C);
    float* sbnf = (float*)(smem + CV_C + 512);

    if (BN && tid < 128) {
        float m = g_bnsum[bnstep][tid] * (1.f / (float)Nn);
        float v = g_bnsq[bnstep][tid] * (1.f / (float)Nn) - m * m;
        float sc = bng[tid] * rsqrtf(v + EPSf);
        sbns[tid] = sc;
        sbnf[tid] = bnb[tid] - m * sc;
    }
    {
        const uint4* ph = ((const uint4*)g_whi) + (size_t)slot * 2048;
        const uint4* pl = ((const uint4*)g_wlo) + (size_t)slot * 2048;
        for (int i = tid; i < 2048; i += 256) {
            int row = i >> 4, c = i & 15;
            *(uint4*)(smem + CV_W + row * 272 + c * 16) = ph[row * 16 + c];
            *(uint4*)(smem + CV_W + 34816 + row * 272 + c * 16) = pl[row * 16 + c];
        }
    }
    __syncthreads();

    u32 a_lo = (u32)((((lane & 7) + ((lane >> 3) & 1) * 8) * 136 + (lane >> 4) * 8) * 2);
    u32 b_lo = (u32)((((lane & 7) + ((lane >> 4) & 1) * 8) * 136 + ((lane >> 3) & 1) * 8) * 2);

    for (int t = blockIdx.x; t < nT; t += gridDim.x) {
        int tb = t * 64;

        for (int idx = tid; idx < 2048; idx += 256) {
            int row = idx >> 5, c4 = idx & 31;
            int gr = min(tb + row, Nn - 1);
            float4 v = ((const float4*)in)[(size_t)gr * 32 + c4];
            if (BN) {
                int c = c4 * 4;
                v.x = fmaf(v.x, sbns[c],     sbnf[c]);
                v.y = fmaf(v.y, sbns[c + 1], sbnf[c + 1]);
                v.z = fmaf(v.z, sbns[c + 2], sbnf[c + 2]);
                v.w = fmaf(v.w, sbns[c + 3], sbnf[c + 3]);
            }
            __nv_bfloat16 h0 = __float2bfloat16(v.x), h1 = __float2bfloat16(v.y);
            __nv_bfloat16 h2 = __float2bfloat16(v.z), h3 = __float2bfloat16(v.w);
            u32 hi01 = bfpack(h0, h1), hi23 = bfpack(h2, h3);
            u32 lo01 = bfpack(__float2bfloat16(v.x - __bfloat162float(h0)),
                              __float2bfloat16(v.y - __bfloat162float(h1)));
            u32 lo23 = bfpack(__float2bfloat16(v.z - __bfloat162float(h2)),
                              __float2bfloat16(v.w - __bfloat162float(h3)));
            *(uint2*)(smem + (size_t)(row * 136 + c4 * 4) * 2) = make_uint2(hi01, hi23);
            *(uint2*)(smem + CV_AL + (size_t)(row * 136 + c4 * 4) * 2) = make_uint2(lo01, lo23);
        }
        __syncthreads();

        float acc[8][4];
        #pragma unroll
        for (int j = 0; j < 8; j++)
            #pragma unroll
            for (int k = 0; k < 4; k++) acc[j][k] = 0.f;

        u32 ab_hi = sb + (u32)(wr * 16 * 272) + a_lo;
        u32 ab_lo = ab_hi + CV_AL;
        u32 bb_hi = sb + CV_W + (u32)(wc * 64 * 272) + b_lo;
        u32 bb_lo = bb_hi + 34816;

        #pragma unroll
        for (int ks = 0; ks < 8; ks++) {
            u32 ah[4], alo[4];
            ldsm4(ab_hi + ks * 32, ah[0], ah[1], ah[2], ah[3]);
            ldsm4(ab_lo + ks * 32, alo[0], alo[1], alo[2], alo[3]);
            u32 bh[8][2], bl[8][2];
            #pragma unroll
            for (int np = 0; np < 4; np++) {
                u32 r0, r1, r2, r3;
                ldsm4(bb_hi + np * (16 * 272) + ks * 32, r0, r1, r2, r3);
                bh[np * 2][0] = r0; bh[np * 2][1] = r1;
                bh[np * 2 + 1][0] = r2; bh[np * 2 + 1][1] = r3;
                ldsm4(bb_lo + np * (16 * 272) + ks * 32, r0, r1, r2, r3);
                bl[np * 2][0] = r0; bl[np * 2][1] = r1;
                bl[np * 2 + 1][0] = r2; bl[np * 2 + 1][1] = r3;
            }
            #pragma unroll
            for (int nt = 0; nt < 8; nt++) {
                mma16816(acc[nt], ah, bh[nt]);
                mma16816(acc[nt], ah, bl[nt]);
                mma16816(acc[nt], alo, bh[nt]);
            }
        }
        __syncthreads();

        int r0 = wr * 16 + gid;
        int gr0 = tb + r0, gr1 = gr0 + 8;
        #pragma unroll
        for (int nt = 0; nt < 8; nt++) {
            int c = wc * 64 + nt * 8 + tig * 2;
            if (gr0 < Nn)
                *(__half2*)&g_h16[(size_t)gr0 * D + c] =
                    __floats2half2_rn(acc[nt][0], acc[nt][1]);
            if (gr1 < Nn)
                *(__half2*)&g_h16[(size_t)gr1 * D + c] =
                    __floats2half2_rn(acc[nt][2], acc[nt][3]);
        }
        __syncthreads();
    }
}

// ---------------- persistent fused MLP kernel (raw mma, R7 geometry) ----------------
// EPI: 0 = LN -> out; 1 = LN -> red2 scatter g_acc[esrc];
//      3 = LN + scatter-mean mix -> out (node encoder)
template <int KIN, int NL, int EPI>
__global__ void __launch_bounds__(256, 1) k_fused(
    const float* __restrict__ in,
    int slot0, int slot1, int slot2,
    const float* __restrict__ wb0, const float* __restrict__ wb1, const float* __restrict__ wb2,
    const float* __restrict__ W1, const float* __restrict__ bias1,
    const float* __restrict__ lng, const float* __restrict__ lnb,
    float* __restrict__ out, const int* __restrict__ esrc, int M, int nT)
{
    constexpr bool PRE = (NL <= 2);
    constexpr int NW = PRE ? NL : 1;
    constexpr int OFF_AL = 34816;
    constexpr int OFF_W = 69632;
    constexpr int OFF_W1S = OFF_W + NW * 69632;
    constexpr int OFF_C = OFF_W1S + (KIN > 0 ? KIN * 512 : 0);
    extern __shared__ char smem[];
    u32 sb = smem_u32(smem);

    int tid = threadIdx.x, lane = tid & 31, wid = tid >> 5;
    int wr = wid & 3, wc = wid >> 2, gid = lane >> 2, tig = lane & 3;

    float* sbias0 = (float*)(smem + OFF_C);
    float* sbias1 = (float*)(smem + OFF_C + 512);
    float* sbias2 = (float*)(smem + OFF_C + 1024);
    float* sg  = (float*)(smem + OFF_C + 1536);
    float* sl  = (float*)(smem + OFF_C + 2048);
    float* sb1 = (float*)(smem + OFF_C + 2560);
    float* rs  = (float*)(smem + OFF_C + 3072);
    float* rq  = (float*)(smem + OFF_C + 4096);
    float* sbias[3] = {sbias0, sbias1, sbias2};

    int slots[3] = {slot0, slot1, slot2};
    const float* wbs[3] = {wb0, wb1, wb2};

    if (tid < 128) {
        #pragma unroll
        for (int l = 0; l < NL; l++) sbias[l][tid] = wbs[l][tid];
        sg[tid] = lng[tid]; sl[tid] = lnb[tid];
        if (KIN > 0) sb1[tid] = bias1[tid];
    }
    if (KIN > 0) {
        float* W1s = (float*)(smem + OFF_W1S);
        for (int i = tid; i < KIN * 128; i += 256) W1s[i] = W1[i];
    }
    if (PRE) {
        #pragma unroll
        for (int l = 0; l < NL; l++) {
            const uint4* ph = ((const uint4*)g_whi) + (size_t)slots[l] * 2048;
            const uint4* pl = ((const uint4*)g_wlo) + (size_t)slots[l] * 2048;
            char* dh = smem + OFF_W + l * 69632;
            for (int i = tid; i < 2048; i += 256) {
                int row = i >> 4, c = i & 15;
                *(uint4*)(dh + row * 272 + c * 16) = ph[row * 16 + c];
                *(uint4*)(dh + 34816 + row * 272 + c * 16) = pl[row * 16 + c];
            }
        }
    }
    __syncthreads();

    u32 a_lo = (u32)((((lane & 7) + ((lane >> 3) & 1) * 8) * 136 + (lane >> 4) * 8) * 2);
    u32 b_lo = (u32)((((lane & 7) + ((lane >> 4) & 1) * 8) * 136 + ((lane >> 3) & 1) * 8) * 2);

    for (int t = blockIdx.x; t < nT; t += gridDim.x) {
        int tb = t * 128;

        if (KIN > 0) {
            float* W1s = (float*)(smem + OFF_W1S);
            int r = tid >> 1, half = tid & 1;
            int gr = min(tb + r, M - 1);
            float xv[KIN > 0 ? KIN : 1];
            #pragma unroll
            for (int k = 0; k < KIN; k++) xv[k] = in[(size_t)gr * KIN + k];
            #pragma unroll
            for (int c4 = 0; c4 < 4; c4++) {
                int cbase = half * 64 + c4 * 16;
                float a16[16];
                #pragma unroll
                for (int j = 0; j < 16; j++) a16[j] = sb1[cbase + j];
                #pragma unroll
                for (int k = 0; k < KIN; k++) {
                    float x = xv[k];
                    const float* wrow = &W1s[k * 128 + cbase];
                    #pragma unroll
                    for (int j = 0; j < 16; j++) a16[j] = fmaf(x, wrow[j], a16[j]);
                }
                #pragma unroll
                for (int j = 0; j < 16; j += 2) {
                    float z0 = leaky(a16[j]), z1 = leaky(a16[j + 1]);
                    __nv_bfloat16 h0 = __float2bfloat16(z0), h1 = __float2bfloat16(z1);
                    *(u32*)(smem + (size_t)(r * 136 + cbase + j) * 2) = bfpack(h0, h1);
                    *(u32*)(smem + OFF_AL + (size_t)(r * 136 + cbase + j) * 2) =
                        bfpack(__float2bfloat16(z0 - __bfloat162float(h0)),
                               __float2bfloat16(z1 - __bfloat162float(h1)));
                }
            }
        } else {
            for (int idx = tid; idx < 4096; idx += 256) {
                int row = idx >> 5, c4 = idx & 31;
                int gr = min(tb + row, M - 1);
                float4 v = ((const float4*)in)[(size_t)gr * 32 + c4];
                __nv_bfloat16 h0 = __float2bfloat16(v.x), h1 = __float2bfloat16(v.y);
                __nv_bfloat16 h2 = __float2bfloat16(v.z), h3 = __float2bfloat16(v.w);
                u32 hi01 = bfpack(h0, h1), hi23 = bfpack(h2, h3);
                u32 lo01 = bfpack(__float2bfloat16(v.x - __bfloat162float(h0)),
                                  __float2bfloat16(v.y - __bfloat162float(h1)));
                u32 lo23 = bfpack(__float2bfloat16(v.z - __bfloat162float(h2)),
                                  __float2bfloat16(v.w - __bfloat162float(h3)));
                *(uint2*)(smem + (size_t)(row * 136 + c4 * 4) * 2) = make_uint2(hi01, hi23);
                *(uint2*)(smem + OFF_AL + (size_t)(row * 136 + c4 * 4) * 2) = make_uint2(lo01, lo23);
            }
        }
        __syncthreads();

        #pragma unroll
        for (int l = 0; l < NL; l++) {
            u32 wbase;
            if (PRE) {
                wbase = sb + OFF_W + l * 69632;
            } else {
                const uint4* ph = ((const uint4*)g_whi) + (size_t)slots[l] * 2048;
                const uint4* pl = ((const uint4*)g_wlo) + (size_t)slots[l] * 2048;
                for (int i = tid; i < 2048; i += 256) {
                    int row = i >> 4, c = i & 15;
                    *(uint4*)(smem + OFF_W + row * 272 + c * 16) = ph[row * 16 + c];
                    *(uint4*)(smem + OFF_W + 34816 + row * 272 + c * 16) = pl[row * 16 + c];
                }
                __syncthreads();
                wbase = sb + OFF_W;
            }

            float acc[2][8][4];
            #pragma unroll
            for (int i = 0; i < 2; i++)
                #pragma unroll
                for (int j = 0; j < 8; j++)
                    #pragma unroll
                    for (int k = 0; k < 4; k++) acc[i][j][k] = 0.f;

            u32 ab_hi = sb + (u32)(wr * 32 * 272) + a_lo;
            u32 ab_lo = ab_hi + OFF_AL;
            u32 bb_hi = wbase + (u32)(wc * 64 * 272) + b_lo;
            u32 bb_lo = bb_hi + 34816;

            #pragma unroll
            for (int ks = 0; ks < 8; ks++) {
                u32 ah[2][4], alo[2][4];
                #pragma unroll
                for (int rt = 0; rt < 2; rt++) {
                    ldsm4(ab_hi + rt * (16 * 272) + ks * 32,
                          ah[rt][0], ah[rt][1], ah[rt][2], ah[rt][3]);
                    ldsm4(ab_lo + rt * (16 * 272) + ks * 32,
                          alo[rt][0], alo[rt][1], alo[rt][2], alo[rt][3]);
                }
                u32 bh[8][2], bl[8][2];
                #pragma unroll
                for (int np = 0; np < 4; np++) {
                    u32 r0, r1, r2, r3;
                    ldsm4(bb_hi + np * (16 * 272) + ks * 32, r0, r1, r2, r3);
                    bh[np * 2][0] = r0; bh[np * 2][1] = r1;
                    bh[np * 2 + 1][0] = r2; bh[np * 2 + 1][1] = r3;
                    ldsm4(bb_lo + np * (16 * 272) + ks * 32, r0, r1, r2, r3);
                    bl[np * 2][0] = r0; bl[np * 2][1] = r1;
                    bl[np * 2 + 1][0] = r2; bl[np * 2 + 1][1] = r3;
                }
                #pragma unroll
                for (int rt = 0; rt < 2; rt++)
                    #pragma unroll
                    for (int nt = 0; nt < 8; nt++) {
                        mma16816(acc[rt][nt], ah[rt], bh[nt]);
                        mma16816(acc[rt][nt], ah[rt], bl[nt]);
                        mma16816(acc[rt][nt], alo[rt], bh[nt]);
                    }
            }
            __syncthreads();

            if (l < NL - 1) {
                const float* bias = sbias[l];
                #pragma unroll
                for (int rt = 0; rt < 2; rt++) {
                    int r0 = wr * 32 + rt * 16 + gid;
                    #pragma unroll
                    for (int nt = 0; nt < 8; nt++) {
                        int c = wc * 64 + nt * 8 + tig * 2;
                        float b0v = bias[c], b1v = bias[c + 1];
                        float z0 = leaky(acc[rt][nt][0] + b0v);
                        float z1 = leaky(acc[rt][nt][1] + b1v);
                        float z2 = leaky(acc[rt][nt][2] + b0v);
                        float z3 = leaky(acc[rt][nt][3] + b1v);
                        __nv_bfloat16 h0 = __float2bfloat16(z0), h1 = __float2bfloat16(z1);
                        __nv_bfloat16 h2 = __float2bfloat16(z2), h3 = __float2bfloat16(z3);
                        *(u32*)(smem + (size_t)(r0 * 136 + c) * 2) = bfpack(h0, h1);
                        *(u32*)(smem + OFF_AL + (size_t)(r0 * 136 + c) * 2) =
                            bfpack(__float2bfloat16(z0 - __bfloat162float(h0)),
                                   __float2bfloat16(z1 - __bfloat162float(h1)));
                        *(u32*)(smem + (size_t)((r0 + 8) * 136 + c) * 2) = bfpack(h2, h3);
                        *(u32*)(smem + OFF_AL + (size_t)((r0 + 8) * 136 + c) * 2) =
                            bfpack(__float2bfloat16(z2 - __bfloat162float(h2)),
                                   __float2bfloat16(z3 - __bfloat162float(h3)));
                    }
                }
                __syncthreads();
            } else {
                const float* bias = sbias[NL - 1];
                #pragma unroll
                for (int rt = 0; rt < 2; rt++) {
                    float s0 = 0.f, q0 = 0.f, s1 = 0.f, q1 = 0.f;
                    #pragma unroll
                    for (int nt = 0; nt < 8; nt++) {
                        int c = wc * 64 + nt * 8 + tig * 2;
                        float b0v = bias[c], b1v = bias[c + 1];
                        float z0 = acc[rt][nt][0] + b0v, z1 = acc[rt][nt][1] + b1v;
                        float z2 = acc[rt][nt][2] + b0v, z3 = acc[rt][nt][3] + b1v;
                        s0 += z0 + z1; q0 += z0 * z0 + z1 * z1;
                        s1 += z2 + z3; q1 += z2 * z2 + z3 * z3;
                    }
                    s0 += __shfl_xor_sync(0xffffffffu, s0, 1);
                    q0 += __shfl_xor_sync(0xffffffffu, q0, 1);
                    s1 += __shfl_xor_sync(0xffffffffu, s1, 1);
                    q1 += __shfl_xor_sync(0xffffffffu, q1, 1);
                    s0 += __shfl_xor_sync(0xffffffffu, s0, 2);
                    q0 += __shfl_xor_sync(0xffffffffu, q0, 2);
                    s1 += __shfl_xor_sync(0xffffffffu, s1, 2);
                    q1 += __shfl_xor_sync(0xffffffffu, q1, 2);
                    int r0 = wr * 32 + rt * 16 + gid;
                    if (tig == 0) {
                        rs[r0 * 2 + wc] = s0; rq[r0 * 2 + wc] = q0;
                        rs[(r0 + 8) * 2 + wc] = s1; rq[(r0 + 8) * 2 + wc] = q1;
                    }
                }
                __syncthreads();
                #pragma unroll
                for (int rt = 0; rt < 2; rt++) {
                    int r0 = wr * 32 + rt * 16 + gid;
                    float S0 = rs[r0 * 2] + rs[r0 * 2 + 1];
                    float Q0 = rq[r0 * 2] + rq[r0 * 2 + 1];
                    float S1 = rs[(r0 + 8) * 2] + rs[(r0 + 8) * 2 + 1];
                    float Q1 = rq[(r0 + 8) * 2] + rq[(r0 + 8) * 2 + 1];
                    float m0 = S0 * (1.f / (float)D);
                    float i0 = rsqrtf(Q0 * (1.f / (float)D) - m0 * m0 + EPSf);
                    float m1 = S1 * (1.f / (float)D);
                    float i1 = rsqrtf(Q1 * (1.f / (float)D) - m1 * m1 + EPSf);
                    int gr0 = tb + r0, gr1 = gr0 + 8;
                    int sidx0 = 0, sidx1 = 0;
                    if (EPI == 1) {
                        if (gr0 < M) sidx0 = esrc[gr0];
                        if (gr1 < M) sidx1 = esrc[gr1];
                    }
                    float ic0 = 0.f, ic1 = 0.f;
                    if (EPI == 3) {
                        if (gr0 < M) ic0 = 1.f / fmaxf(g_cnt[gr0], 1.f);
                        if (gr1 < M) ic1 = 1.f / fmaxf(g_cnt[gr1], 1.f);
                    }
                    #pragma unroll
                    for (int nt = 0; nt < 8; nt++) {
                        int c = wc * 64 + nt * 8 + tig * 2;
                        float b0v = bias[c], b1v = bias[c + 1];
                        float g0 = sg[c], g1 = sg[c + 1];
                        float l0 = sl[c], l1 = sl[c + 1];
                        float o0 = (acc[rt][nt][0] + b0v - m0) * i0 * g0 + l0;
                        float o1 = (acc[rt][nt][1] + b1v - m0) * i0 * g1 + l1;
                        float o2 = (acc[rt][nt][2] + b0v - m1) * i1 * g0 + l0;
                        float o3 = (acc[rt][nt][3] + b1v - m1) * i1 * g1 + l1;
                        if (EPI == 0) {
                            if (gr0 < M) *(float2*)&out[(size_t)gr0 * D + c] = make_float2(o0, o1);
                            if (gr1 < M) *(float2*)&out[(size_t)gr1 * D + c] = make_float2(o2, o3);
                        } else if (EPI == 3) {
                            if (gr0 < M) {
                                float2 ac = *(const float2*)&g_acc[(size_t)gr0 * D + c];
                                *(float2*)&out[(size_t)gr0 * D + c] =
                                    make_float2(o0 + ac.x * ic0, o1 + ac.y * ic0);
                            }
                            if (gr1 < M) {
                                float2 ac = *(const float2*)&g_acc[(size_t)gr1 * D + c];
                                *(float2*)&out[(size_t)gr1 * D + c] =
                                    make_float2(o2 + ac.x * ic1, o3 + ac.y * ic1);
                            }
                        } else {
                            if (gr0 < M) red2(&g_acc[(size_t)sidx0 * D + c], o0, o1);
                            if (gr1 < M) red2(&g_acc[(size_t)sidx1 * D + c], o2, o3);
                        }
                    }
                }
                __syncthreads();
            }
        }
    }
}

// ---------------- host orchestration ----------------
extern "C" void kernel_launch(void* const* d_in, const int* in_sizes, int n_in,
                              void* d_out, int out_size)
{
    const float* node_feat = (const float*)d_in[0];
    const float* edge_feat = (const float*)d_in[1];
    const int*   ei        = (const int*)d_in[2];
    const float* enW1 = (const float*)d_in[3];  const float* enb1 = (const float*)d_in[4];
    const float* enW2 = (const float*)d_in[5];  const float* enb2 = (const float*)d_in[6];
    const float* enW3 = (const float*)d_in[7];  const float* enb3 = (const float*)d_in[8];
    const float* enlg = (const float*)d_in[9];  const float* enlb = (const float*)d_in[10];
    const float* eeW1 = (const float*)d_in[11]; const float* eeb1 = (const float*)d_in[12];
    const float* eeW2 = (const float*)d_in[13]; const float* eeb2 = (const float*)d_in[14];
    const float* eeW3 = (const float*)d_in[15]; const float* eeb3 = (const float*)d_in[16];
    const float* eelg = (const float*)d_in[17]; const float* eelb = (const float*)d_in[18];
    const float* procW = (const float*)d_in[19];
    const float* procb = (const float*)d_in[20];
    const float* bng   = (const float*)d_in[21];
    const float* bnb   = (const float*)d_in[22];
    const float* dW1 = (const float*)d_in[23]; const float* db1 = (const float*)d_in[24];
    const float* dW2 = (const float*)d_in[25]; const float* db2 = (const float*)d_in[26];
    const float* dW3 = (const float*)d_in[27]; const float* db3 = (const float*)d_in[28];
    const float* dlg = (const float*)d_in[29]; const float* dlb = (const float*)d_in[30];
    float* out = (float*)d_out;

    float* hn_ptr = nullptr; cudaGetSymbolAddress((void**)&hn_ptr, g_hn);
    float* y_ptr = nullptr;  cudaGetSymbolAddress((void**)&y_ptr, g_y);

    const int SM_EDGE = 69632 + 2 * 69632 + EDGE_IN * 512 + 5120;   // 216064
    const int SM_NODE = 69632 + 2 * 69632 + NODE_IN * 512 + 5120;   // 223744
    const int SM_DEC  = 69632 + 1 * 69632 + 5120;                    // 144384

    cudaFuncSetAttribute(k_fused<EDGE_IN, 2, 1>, cudaFuncAttributeMaxDynamicSharedMemorySize, SM_EDGE);
    cudaFuncSetAttribute(k_fused<NODE_IN, 2, 3>, cudaFuncAttributeMaxDynamicSharedMemorySize, SM_NODE);
    cudaFuncSetAttribute(k_fused<0, 3, 0>, cudaFuncAttributeMaxDynamicSharedMemorySize, SM_DEC);
    cudaFuncSetAttribute(k_conv<false>, cudaFuncAttributeMaxDynamicSharedMemorySize, SM_CONV);
    cudaFuncSetAttribute(k_conv<true>,  cudaFuncAttributeMaxDynamicSharedMemorySize, SM_CONV);

    int NnT = (Nn + 127) / 128, EeT = Ee / 128;
    int NnT64 = (Nn + 63) / 64;
    int G = 148, G2 = 296;

    // 1: weight splits   2: zero   3: count
    k_wsplit_all<<<dim3(64, NSLOT), 256>>>(enW2, enW3, eeW2, eeW3, procW, dW1, dW2, dW3);
    k_zero<<<512, 256>>>();
    k_count<<<(Ee + 255) / 256, 256>>>(ei);
    // 4: edge encoder (profiled) — LN + scatter-sum into g_acc
    k_fused<EDGE_IN, 2, 1><<<G, 256, SM_EDGE>>>(
        edge_feat, 2, 3, 0, eeb2, eeb3, nullptr, eeW1, eeb1, eelg, eelb,
        nullptr, ei, Ee, EeT);
    // 5: node encoder with fused scatter-mean mix -> g_hn
    k_fused<NODE_IN, 2, 3><<<G, 256, SM_NODE>>>(
        node_feat, 0, 1, 0, enb2, enb3, nullptr, enW1, enb1, enlg, enlb,
        hn_ptr, nullptr, Nn, NnT);
    // CSR build
    k_scan<<<1, 1024>>>();
    k_dis<<<(Nn + 255) / 256, 256>>>();
    k_fill<<<(Ee + 255) / 256, 256>>>(ei);

    // processor steps
    for (int s = 0; s < STEPS; s++) {
        const float* b0 = procb + (size_t)(s * 2 + 0) * D;
        const float* b1 = procb + (size_t)(s * 2 + 1) * D;

        k_conv<false><<<G2, 256, SM_CONV>>>(hn_ptr, 4 + 2 * s, 0, nullptr, nullptr, NnT64);
        k_gatherA<<<592, 256>>>(b0, s);
        k_conv<true><<<G2, 256, SM_CONV>>>(y_ptr, 5 + 2 * s, s,
                                           bng + (size_t)s * D, bnb + (size_t)s * D, NnT64);
        k_gatherB<<<592, 256>>>(b1);
    }

    // decoder (3 layers + LN, per-layer W reload)
    k_fused<0, 3, 0><<<G, 256, SM_DEC>>>(
        hn_ptr, 14, 15, 16, db1, db2, db3,
        nullptr, nullptr, dlg, dlb, out, nullptr, Nn, NnT);
}

// round 14
// speedup vs baseline: 1.7340x; 1.2538x over previous
#include <cuda_runtime.h>
#include <cuda_bf16.h>
#include <cuda_fp16.h>
#include <cstddef>
#include <cstdint>

#define Nn 50000
#define Ee 800000
#define D 128
#define NODE_IN 19
#define EDGE_IN 4
#define STEPS 5
#define EPSf 1e-5f

typedef unsigned long long u64;
typedef unsigned int u32;

// ---------------- device scratch ----------------
__device__ float g_hn[Nn * D];
__device__ float g_acc[Nn * D];
__device__ __half g_h16[Nn * D];
__device__ float g_y[Nn * D];
__device__ float g_cnt[Nn];
__device__ float g_dis[Nn];
__device__ int   g_degi[Nn];
__device__ int   g_fill[Nn];
__device__ int   g_rowoff[Nn + 1];
__device__ int   g_csrs[Ee];
__device__ float g_csrw[Ee];
__device__ float g_bnsum[STEPS][D];
__device__ float g_bnsq[STEPS][D];

#define NSLOT 17
__device__ __nv_bfloat16 g_whi[NSLOT * D * D];
__device__ __nv_bfloat16 g_wlo[NSLOT * D * D];
__device__ __half        g_w16[NSLOT * D * D];

__device__ __forceinline__ float leaky(float v) { return v > 0.f ? v : 0.05f * v; }

__device__ __forceinline__ void red4(float* p, float a, float b, float c, float d) {
    asm volatile("red.global.add.v4.f32 [%0], {%1,%2,%3,%4};"
                 :: "l"(p), "f"(a), "f"(b), "f"(c), "f"(d) : "memory");
}
__device__ __forceinline__ void red2(float* p, float a, float b) {
    asm volatile("red.global.add.v2.f32 [%0], {%1,%2};"
                 :: "l"(p), "f"(a), "f"(b) : "memory");
}
__device__ __forceinline__ u32 bfpack(__nv_bfloat16 a, __nv_bfloat16 b) {
    __nv_bfloat162 t = __halves2bfloat162(a, b);
    return *(u32*)&t;
}
__device__ __forceinline__ u32 hpack(float a, float b) {
    __half2 t = __floats2half2_rn(a, b);
    return *(u32*)&t;
}
__device__ __forceinline__ u32 smem_u32(const void* p) {
    u32 a; asm("{ .reg .u64 t; cvta.to.shared.u64 t, %1; cvt.u32.u64 %0, t; }"
               : "=r"(a) : "l"(p));
    return a;
}
__device__ __forceinline__ void ldsm4(u32 addr, u32& r0, u32& r1, u32& r2, u32& r3) {
    asm volatile("ldmatrix.sync.aligned.m8n8.x4.shared.b16 {%0,%1,%2,%3}, [%4];"
                 : "=r"(r0), "=r"(r1), "=r"(r2), "=r"(r3) : "r"(addr));
}
__device__ __forceinline__ void mma16816(float* c, const u32* a, const u32* b) {
    asm volatile("mma.sync.aligned.m16n8k16.row.col.f32.bf16.bf16.f32 "
                 "{%0,%1,%2,%3}, {%4,%5,%6,%7}, {%8,%9}, {%0,%1,%2,%3};"
                 : "+f"(c[0]), "+f"(c[1]), "+f"(c[2]), "+f"(c[3])
                 : "r"(a[0]), "r"(a[1]), "r"(a[2]), "r"(a[3]), "r"(b[0]), "r"(b[1]));
}
__device__ __forceinline__ void mma16816h(float* c, const u32* a, const u32* b) {
    asm volatile("mma.sync.aligned.m16n8k16.row.col.f32.f16.f16.f32 "
                 "{%0,%1,%2,%3}, {%4,%5,%6,%7}, {%8,%9}, {%0,%1,%2,%3};"
                 : "+f"(c[0]), "+f"(c[1]), "+f"(c[2]), "+f"(c[3])
                 : "r"(a[0]), "r"(a[1]), "r"(a[2]), "r"(a[3]), "r"(b[0]), "r"(b[1]));
}

__device__ __forceinline__ float4 h16_load(int row, int c0) {
    uint2 raw = *(const uint2*)&g_h16[(size_t)row * D + c0];
    __half2 p0 = *(__half2*)&raw.x;
    __half2 p1 = *(__half2*)&raw.y;
    float2 f0 = __half22float2(p0);
    float2 f1 = __half22float2(p1);
    return make_float4(f0.x, f0.y, f1.x, f1.y);
}

// ---------------- utility kernels ----------------
__global__ void k_zero() {
    int i = blockIdx.x * blockDim.x + threadIdx.x;
    int stride = gridDim.x * blockDim.x;
    for (int j = i; j < Nn * D; j += stride) g_acc[j] = 0.f;
    for (int j = i; j < Nn; j += stride) {
        g_cnt[j] = 0.f; g_degi[j] = 0; g_fill[j] = 0;
    }
    if (i < STEPS * D) { (&g_bnsum[0][0])[i] = 0.f; (&g_bnsq[0][0])[i] = 0.f; }
}

__global__ void k_count(const int* __restrict__ ei) {
    int e = blockIdx.x * blockDim.x + threadIdx.x;
    if (e >= Ee) return;
    atomicAdd(&g_cnt[ei[e]], 1.f);
    atomicAdd(&g_degi[ei[Ee + e]], 1);
}

__global__ void k_scan() {
    __shared__ int ts[1024];
    int t = threadIdx.x;
    const int CH = (Nn + 1023) / 1024;
    int start = t * CH;
    int end = min(start + CH, Nn);
    int sum = 0;
    for (int i = start; i < end; i++) sum += g_degi[i];
    ts[t] = sum;
    __syncthreads();
    for (int off = 1; off < 1024; off <<= 1) {
        int v = (t >= off) ? ts[t - off] : 0;
        __syncthreads();
        ts[t] += v;
        __syncthreads();
    }
    int run = (t == 0) ? 0 : ts[t - 1];
    for (int i = start; i < end; i++) { g_rowoff[i] = run; run += g_degi[i]; }
    if (t == 1023) g_rowoff[Nn] = run;
}

__global__ void k_dis() {
    int i = blockIdx.x * blockDim.x + threadIdx.x;
    if (i < Nn) g_dis[i] = rsqrtf((float)g_degi[i] + 1.0f);
}

__global__ void k_fill(const int* __restrict__ ei) {
    int e = blockIdx.x * blockDim.x + threadIdx.x;
    if (e >= Ee) return;
    int s = ei[e], d = ei[Ee + e];
    int pos = g_rowoff[d] + atomicAdd(&g_fill[d], 1);
    g_csrs[pos] = s;
    g_csrw[pos] = g_dis[s] * g_dis[d];
}

// ---------------- CSR gather (warp per node, 4-edge unroll, fp16 h) ----------------
__device__ __forceinline__ float4 gather_node(int node, int c0) {
    float dd = g_dis[node];
    float d2 = dd * dd;
    float4 a = h16_load(node, c0);
    a.x *= d2; a.y *= d2; a.z *= d2; a.w *= d2;
    int p = g_rowoff[node], p1 = g_rowoff[node + 1];
    for (; p + 3 < p1; p += 4) {
        int sA = g_csrs[p];     float wA = g_csrw[p];
        int sB = g_csrs[p + 1]; float wB = g_csrw[p + 1];
        int sC = g_csrs[p + 2]; float wC = g_csrw[p + 2];
        int sD = g_csrs[p + 3]; float wD = g_csrw[p + 3];
        float4 vA = h16_load(sA, c0);
        float4 vB = h16_load(sB, c0);
        float4 vC = h16_load(sC, c0);
        float4 vD = h16_load(sD, c0);
        a.x = fmaf(vA.x, wA, a.x); a.y = fmaf(vA.y, wA, a.y);
        a.z = fmaf(vA.z, wA, a.z); a.w = fmaf(vA.w, wA, a.w);
        a.x = fmaf(vB.x, wB, a.x); a.y = fmaf(vB.y, wB, a.y);
        a.z = fmaf(vB.z, wB, a.z); a.w = fmaf(vB.w, wB, a.w);
        a.x = fmaf(vC.x, wC, a.x); a.y = fmaf(vC.y, wC, a.y);
        a.z = fmaf(vC.z, wC, a.z); a.w = fmaf(vC.w, wC, a.w);
        a.x = fmaf(vD.x, wD, a.x); a.y = fmaf(vD.y, wD, a.y);
        a.z = fmaf(vD.z, wD, a.z); a.w = fmaf(vD.w, wD, a.w);
    }
    for (; p < p1; p++) {
        int sA = g_csrs[p]; float wA = g_csrw[p];
        float4 vA = h16_load(sA, c0);
        a.x = fmaf(vA.x, wA, a.x); a.y = fmaf(vA.y, wA, a.y);
        a.z = fmaf(vA.z, wA, a.z); a.w = fmaf(vA.w, wA, a.w);
    }
    return a;
}

__global__ void __launch_bounds__(256) k_gatherA(const float* __restrict__ b0, int step) {
    int lane = threadIdx.x & 31;
    int gw = blockIdx.x * 8 + (threadIdx.x >> 5);
    int nw = gridDim.x * 8;
    int c0 = lane * 4;
    float4 bb = *(const float4*)&b0[c0];
    float s0 = 0.f, s1 = 0.f, s2 = 0.f, s3 = 0.f;
    float q0 = 0.f, q1 = 0.f, q2 = 0.f, q3 = 0.f;

    for (int node = gw; node < Nn; node += nw) {
        float4 a = gather_node(node, c0);
        float v0 = leaky(a.x + bb.x), v1 = leaky(a.y + bb.y);
        float v2 = leaky(a.z + bb.z), v3 = leaky(a.w + bb.w);
        *(float4*)&g_y[(size_t)node * D + c0] = make_float4(v0, v1, v2, v3);
        s0 += v0; s1 += v1; s2 += v2; s3 += v3;
        q0 += v0 * v0; q1 += v1 * v1; q2 += v2 * v2; q3 += v3 * v3;
    }
    red4(&g_bnsum[step][c0], s0, s1, s2, s3);
    red4(&g_bnsq[step][c0],  q0, q1, q2, q3);
}

__global__ void __launch_bounds__(256) k_gatherB(const float* __restrict__ b1) {
    int lane = threadIdx.x & 31;
    int gw = blockIdx.x * 8 + (threadIdx.x >> 5);
    int nw = gridDim.x * 8;
    int c0 = lane * 4;
    float4 bb = *(const float4*)&b1[c0];

    for (int node = gw; node < Nn; node += nw) {
        float4 a = gather_node(node, c0);
        float4 h4 = *(const float4*)&g_hn[(size_t)node * D + c0];
        h4.x += a.x + bb.x; h4.y += a.y + bb.y;
        h4.z += a.z + bb.z; h4.w += a.w + bb.w;
        *(float4*)&g_hn[(size_t)node * D + c0] = h4;
    }
}

// all 17 weight splits (bf16 hi/lo + fp16): grid (64, 17)
__global__ void k_wsplit_all(
    const float* __restrict__ enW2, const float* __restrict__ enW3,
    const float* __restrict__ eeW2, const float* __restrict__ eeW3,
    const float* __restrict__ procW,
    const float* __restrict__ dW1, const float* __restrict__ dW2,
    const float* __restrict__ dW3)
{
    int slot = blockIdx.y;
    const float* W;
    if (slot == 0) W = enW2;
    else if (slot == 1) W = enW3;
    else if (slot == 2) W = eeW2;
    else if (slot == 3) W = eeW3;
    else if (slot < 14) W = procW + (size_t)(slot - 4) * D * D;
    else if (slot == 14) W = dW1;
    else if (slot == 15) W = dW2;
    else W = dW3;
    int i = blockIdx.x * 256 + threadIdx.x;
    int k = i >> 7, n = i & 127;
    float v = W[i];
    __nv_bfloat16 h = __float2bfloat16(v);
    g_whi[slot * D * D + n * D + k] = h;
    g_wlo[slot * D * D + n * D + k] = __float2bfloat16(v - __bfloat162float(h));
    g_w16[slot * D * D + n * D + k] = __float2half_rn(v);
}

// ---------------- conv GEMM: 64-row tiles, 2 CTAs/SM, bf16 hi/lo, fp16 output ----------------
#define CV_AL 17408
#define CV_W  34816
#define CV_C  104448
#define SM_CONV 105472

template <bool BN>
__global__ void __launch_bounds__(256, 2) k_conv(
    const float* __restrict__ in, int slot, int bnstep,
    const float* __restrict__ bng, const float* __restrict__ bnb, int nT)
{
    extern __shared__ char smem[];
    u32 sb = smem_u32(smem);
    int tid = threadIdx.x, lane = tid & 31, wid = tid >> 5;
    int wr = wid & 3, wc = wid >> 2, gid = lane >> 2, tig = lane & 3;

    float* sbns = (float*)(smem + CV_C);
    float* sbnf = (float*)(smem + CV_C + 512);

    if (BN && tid < 128) {
        float m = g_bnsum[bnstep][tid] * (1.f / (float)Nn);
        float v = g_bnsq[bnstep][tid] * (1.f / (float)Nn) - m * m;
        float sc = bng[tid] * rsqrtf(v + EPSf);
        sbns[tid] = sc;
        sbnf[tid] = bnb[tid] - m * sc;
    }
    {
        const uint4* ph = ((const uint4*)g_whi) + (size_t)slot * 2048;
        const uint4* pl = ((const uint4*)g_wlo) + (size_t)slot * 2048;
        for (int i = tid; i < 2048; i += 256) {
            int row = i >> 4, c = i & 15;
            *(uint4*)(smem + CV_W + row * 272 + c * 16) = ph[row * 16 + c];
            *(uint4*)(smem + CV_W + 34816 + row * 272 + c * 16) = pl[row * 16 + c];
        }
    }
    __syncthreads();

    u32 a_lo = (u32)((((lane & 7) + ((lane >> 3) & 1) * 8) * 136 + (lane >> 4) * 8) * 2);
    u32 b_lo = (u32)((((lane & 7) + ((lane >> 4) & 1) * 8) * 136 + ((lane >> 3) & 1) * 8) * 2);

    for (int t = blockIdx.x; t < nT; t += gridDim.x) {
        int tb = t * 64;

        for (int idx = tid; idx < 2048; idx += 256) {
            int row = idx >> 5, c4 = idx & 31;
            int gr = min(tb + row, Nn - 1);
            float4 v = ((const float4*)in)[(size_t)gr * 32 + c4];
            if (BN) {
                int c = c4 * 4;
                v.x = fmaf(v.x, sbns[c],     sbnf[c]);
                v.y = fmaf(v.y, sbns[c + 1], sbnf[c + 1]);
                v.z = fmaf(v.z, sbns[c + 2], sbnf[c + 2]);
                v.w = fmaf(v.w, sbns[c + 3], sbnf[c + 3]);
            }
            __nv_bfloat16 h0 = __float2bfloat16(v.x), h1 = __float2bfloat16(v.y);
            __nv_bfloat16 h2 = __float2bfloat16(v.z), h3 = __float2bfloat16(v.w);
            u32 hi01 = bfpack(h0, h1), hi23 = bfpack(h2, h3);
            u32 lo01 = bfpack(__float2bfloat16(v.x - __bfloat162float(h0)),
                              __float2bfloat16(v.y - __bfloat162float(h1)));
            u32 lo23 = bfpack(__float2bfloat16(v.z - __bfloat162float(h2)),
                              __float2bfloat16(v.w - __bfloat162float(h3)));
            *(uint2*)(smem + (size_t)(row * 136 + c4 * 4) * 2) = make_uint2(hi01, hi23);
            *(uint2*)(smem + CV_AL + (size_t)(row * 136 + c4 * 4) * 2) = make_uint2(lo01, lo23);
        }
        __syncthreads();

        float acc[8][4];
        #pragma unroll
        for (int j = 0; j < 8; j++)
            #pragma unroll
            for (int k = 0; k < 4; k++) acc[j][k] = 0.f;

        u32 ab_hi = sb + (u32)(wr * 16 * 272) + a_lo;
        u32 ab_lo = ab_hi + CV_AL;
        u32 bb_hi = sb + CV_W + (u32)(wc * 64 * 272) + b_lo;
        u32 bb_lo = bb_hi + 34816;

        #pragma unroll
        for (int ks = 0; ks < 8; ks++) {
            u32 ah[4], alo[4];
            ldsm4(ab_hi + ks * 32, ah[0], ah[1], ah[2], ah[3]);
            ldsm4(ab_lo + ks * 32, alo[0], alo[1], alo[2], alo[3]);
            u32 bh[8][2], bl[8][2];
            #pragma unroll
            for (int np = 0; np < 4; np++) {
                u32 r0, r1, r2, r3;
                ldsm4(bb_hi + np * (16 * 272) + ks * 32, r0, r1, r2, r3);
                bh[np * 2][0] = r0; bh[np * 2][1] = r1;
                bh[np * 2 + 1][0] = r2; bh[np * 2 + 1][1] = r3;
                ldsm4(bb_lo + np * (16 * 272) + ks * 32, r0, r1, r2, r3);
                bl[np * 2][0] = r0; bl[np * 2][1] = r1;
                bl[np * 2 + 1][0] = r2; bl[np * 2 + 1][1] = r3;
            }
            #pragma unroll
            for (int nt = 0; nt < 8; nt++) {
                mma16816(acc[nt], ah, bh[nt]);
                mma16816(acc[nt], ah, bl[nt]);
                mma16816(acc[nt], alo, bh[nt]);
            }
        }
        __syncthreads();

        int r0 = wr * 16 + gid;
        int gr0 = tb + r0, gr1 = gr0 + 8;
        #pragma unroll
        for (int nt = 0; nt < 8; nt++) {
            int c = wc * 64 + nt * 8 + tig * 2;
            if (gr0 < Nn)
                *(__half2*)&g_h16[(size_t)gr0 * D + c] =
                    __floats2half2_rn(acc[nt][0], acc[nt][1]);
            if (gr1 < Nn)
                *(__half2*)&g_h16[(size_t)gr1 * D + c] =
                    __floats2half2_rn(acc[nt][2], acc[nt][3]);
        }
        __syncthreads();
    }
}

// ---------------- fp16 single-pass fused encoder (persistent) ----------------
// A fp16 [0,34816); W fp16 2 layers at [34816, 104448); W1s fp32; consts.
// EPI: 1 = LN -> red2 scatter g_acc[esrc]; 3 = LN + scatter-mean mix -> out
template <int KIN, int EPI, int MINB>
__global__ void __launch_bounds__(256, MINB) k_f16(
    const float* __restrict__ in, int slot0, int slot1,
    const float* __restrict__ wb0, const float* __restrict__ wb1,
    const float* __restrict__ W1, const float* __restrict__ bias1,
    const float* __restrict__ lng, const float* __restrict__ lnb,
    float* __restrict__ out, const int* __restrict__ esrc, int M, int nT)
{
    constexpr int OFF_W = 34816;
    constexpr int OFF_W1S = OFF_W + 2 * 34816;
    constexpr int OFF_C = OFF_W1S + KIN * 512;
    extern __shared__ char smem[];
    u32 sb = smem_u32(smem);

    int tid = threadIdx.x, lane = tid & 31, wid = tid >> 5;
    int wr = wid & 3, wc = wid >> 2, gid = lane >> 2, tig = lane & 3;

    float* sbias0 = (float*)(smem + OFF_C);
    float* sbias1 = (float*)(smem + OFF_C + 512);
    float* sg  = (float*)(smem + OFF_C + 1024);
    float* sl  = (float*)(smem + OFF_C + 1536);
    float* sb1 = (float*)(smem + OFF_C + 2048);
    float* rs  = (float*)(smem + OFF_C + 2560);   // [128][2]
    float* rq  = (float*)(smem + OFF_C + 3584);   // [128][2]
    float* sbias[2] = {sbias0, sbias1};

    if (tid < 128) {
        sbias0[tid] = wb0[tid]; sbias1[tid] = wb1[tid];
        sg[tid] = lng[tid]; sl[tid] = lnb[tid];
        sb1[tid] = bias1[tid];
    }
    {
        float* W1s = (float*)(smem + OFF_W1S);
        for (int i = tid; i < KIN * 128; i += 256) W1s[i] = W1[i];
        // fp16 W: 16384 halfs = 2048 uint4 per slot; row = 256B data at 272B stride
        const uint4* p0 = ((const uint4*)g_w16) + (size_t)slot0 * 2048;
        const uint4* p1 = ((const uint4*)g_w16) + (size_t)slot1 * 2048;
        for (int i = tid; i < 2048; i += 256) {
            int row = i >> 4, c = i & 15;
            *(uint4*)(smem + OFF_W + row * 272 + c * 16) = p0[row * 16 + c];
            *(uint4*)(smem + OFF_W + 34816 + row * 272 + c * 16) = p1[row * 16 + c];
        }
    }
    __syncthreads();

    u32 a_lo = (u32)((((lane & 7) + ((lane >> 3) & 1) * 8) * 136 + (lane >> 4) * 8) * 2);
    u32 b_lo = (u32)((((lane & 7) + ((lane >> 4) & 1) * 8) * 136 + ((lane >> 3) & 1) * 8) * 2);

    for (int t = blockIdx.x; t < nT; t += gridDim.x) {
        int tb = t * 128;

        // ---- scalar layer-1 -> fp16 A tile ----
        {
            float* W1s = (float*)(smem + OFF_W1S);
            int r = tid >> 1, half = tid & 1;
            int gr = min(tb + r, M - 1);
            float xv[KIN];
            #pragma unroll
            for (int k = 0; k < KIN; k++) xv[k] = in[(size_t)gr * KIN + k];
            #pragma unroll
            for (int c4 = 0; c4 < 4; c4++) {
                int cbase = half * 64 + c4 * 16;
                float a16[16];
                #pragma unroll
                for (int j = 0; j < 16; j++) a16[j] = sb1[cbase + j];
                #pragma unroll
                for (int k = 0; k < KIN; k++) {
                    float x = xv[k];
                    const float* wrow = &W1s[k * 128 + cbase];
                    #pragma unroll
                    for (int j = 0; j < 16; j++) a16[j] = fmaf(x, wrow[j], a16[j]);
                }
                #pragma unroll
                for (int j = 0; j < 16; j += 2)
                    *(u32*)(smem + (size_t)(r * 136 + cbase + j) * 2) =
                        hpack(leaky(a16[j]), leaky(a16[j + 1]));
            }
        }
        __syncthreads();

        // ---- 2 fp16 layers ----
        #pragma unroll
        for (int l = 0; l < 2; l++) {
            u32 wbase = sb + OFF_W + l * 34816;

            float acc[2][8][4];
            #pragma unroll
            for (int i = 0; i < 2; i++)
                #pragma unroll
                for (int j = 0; j < 8; j++)
                    #pragma unroll
                    for (int k = 0; k < 4; k++) acc[i][j][k] = 0.f;

            u32 ab = sb + (u32)(wr * 32 * 272) + a_lo;
            u32 bb = wbase + (u32)(wc * 64 * 272) + b_lo;

            #pragma unroll
            for (int ks = 0; ks < 8; ks++) {
                u32 ah[2][4];
                #pragma unroll
                for (int rt = 0; rt < 2; rt++)
                    ldsm4(ab + rt * (16 * 272) + ks * 32,
                          ah[rt][0], ah[rt][1], ah[rt][2], ah[rt][3]);
                u32 bh[8][2];
                #pragma unroll
                for (int np = 0; np < 4; np++) {
                    u32 r0, r1, r2, r3;
                    ldsm4(bb + np * (16 * 272) + ks * 32, r0, r1, r2, r3);
                    bh[np * 2][0] = r0; bh[np * 2][1] = r1;
                    bh[np * 2 + 1][0] = r2; bh[np * 2 + 1][1] = r3;
                }
                #pragma unroll
                for (int rt = 0; rt < 2; rt++)
                    #pragma unroll
                    for (int nt = 0; nt < 8; nt++)
                        mma16816h(acc[rt][nt], ah[rt], bh[nt]);
            }
            __syncthreads();

            if (l == 0) {
                const float* bias = sbias[0];
                #pragma unroll
                for (int rt = 0; rt < 2; rt++) {
                    int r0 = wr * 32 + rt * 16 + gid;
                    #pragma unroll
                    for (int nt = 0; nt < 8; nt++) {
                        int c = wc * 64 + nt * 8 + tig * 2;
                        float b0v = bias[c], b1v = bias[c + 1];
                        *(u32*)(smem + (size_t)(r0 * 136 + c) * 2) =
                            hpack(leaky(acc[rt][nt][0] + b0v), leaky(acc[rt][nt][1] + b1v));
                        *(u32*)(smem + (size_t)((r0 + 8) * 136 + c) * 2) =
                            hpack(leaky(acc[rt][nt][2] + b0v), leaky(acc[rt][nt][3] + b1v));
                    }
                }
                __syncthreads();
            } else {
                const float* bias = sbias[1];
                #pragma unroll
                for (int rt = 0; rt < 2; rt++) {
                    float s0 = 0.f, q0 = 0.f, s1 = 0.f, q1 = 0.f;
                    #pragma unroll
                    for (int nt = 0; nt < 8; nt++) {
                        int c = wc * 64 + nt * 8 + tig * 2;
                        float b0v = bias[c], b1v = bias[c + 1];
                        float z0 = acc[rt][nt][0] + b0v, z1 = acc[rt][nt][1] + b1v;
                        float z2 = acc[rt][nt][2] + b0v, z3 = acc[rt][nt][3] + b1v;
                        s0 += z0 + z1; q0 += z0 * z0 + z1 * z1;
                        s1 += z2 + z3; q1 += z2 * z2 + z3 * z3;
                    }
                    s0 += __shfl_xor_sync(0xffffffffu, s0, 1);
                    q0 += __shfl_xor_sync(0xffffffffu, q0, 1);
                    s1 += __shfl_xor_sync(0xffffffffu, s1, 1);
                    q1 += __shfl_xor_sync(0xffffffffu, q1, 1);
                    s0 += __shfl_xor_sync(0xffffffffu, s0, 2);
                    q0 += __shfl_xor_sync(0xffffffffu, q0, 2);
                    s1 += __shfl_xor_sync(0xffffffffu, s1, 2);
                    q1 += __shfl_xor_sync(0xffffffffu, q1, 2);
                    int r0 = wr * 32 + rt * 16 + gid;
                    if (tig == 0) {
                        rs[r0 * 2 + wc] = s0; rq[r0 * 2 + wc] = q0;
                        rs[(r0 + 8) * 2 + wc] = s1; rq[(r0 + 8) * 2 + wc] = q1;
                    }
                }
                __syncthreads();
                #pragma unroll
                for (int rt = 0; rt < 2; rt++) {
                    int r0 = wr * 32 + rt * 16 + gid;
                    float S0 = rs[r0 * 2] + rs[r0 * 2 + 1];
                    float Q0 = rq[r0 * 2] + rq[r0 * 2 + 1];
                    float S1 = rs[(r0 + 8) * 2] + rs[(r0 + 8) * 2 + 1];
                    float Q1 = rq[(r0 + 8) * 2] + rq[(r0 + 8) * 2 + 1];
                    float m0 = S0 * (1.f / (float)D);
                    float i0 = rsqrtf(Q0 * (1.f / (float)D) - m0 * m0 + EPSf);
                    float m1 = S1 * (1.f / (float)D);
                    float i1 = rsqrtf(Q1 * (1.f / (float)D) - m1 * m1 + EPSf);
                    int gr0 = tb + r0, gr1 = gr0 + 8;
                    int sidx0 = 0, sidx1 = 0;
                    if (EPI == 1) {
                        if (gr0 < M) sidx0 = esrc[gr0];
                        if (gr1 < M) sidx1 = esrc[gr1];
                    }
                    float ic0 = 0.f, ic1 = 0.f;
                    if (EPI == 3) {
                        if (gr0 < M) ic0 = 1.f / fmaxf(g_cnt[gr0], 1.f);
                        if (gr1 < M) ic1 = 1.f / fmaxf(g_cnt[gr1], 1.f);
                    }
                    #pragma unroll
                    for (int nt = 0; nt < 8; nt++) {
                        int c = wc * 64 + nt * 8 + tig * 2;
                        float b0v = bias[c], b1v = bias[c + 1];
                        float g0 = sg[c], g1 = sg[c + 1];
                        float l0 = sl[c], l1 = sl[c + 1];
                        float o0 = (acc[rt][nt][0] + b0v - m0) * i0 * g0 + l0;
                        float o1 = (acc[rt][nt][1] + b1v - m0) * i0 * g1 + l1;
                        float o2 = (acc[rt][nt][2] + b0v - m1) * i1 * g0 + l0;
                        float o3 = (acc[rt][nt][3] + b1v - m1) * i1 * g1 + l1;
                        if (EPI == 3) {
                            if (gr0 < M) {
                                float2 ac = *(const float2*)&g_acc[(size_t)gr0 * D + c];
                                *(float2*)&out[(size_t)gr0 * D + c] =
                                    make_float2(o0 + ac.x * ic0, o1 + ac.y * ic0);
                            }
                            if (gr1 < M) {
                                float2 ac = *(const float2*)&g_acc[(size_t)gr1 * D + c];
                                *(float2*)&out[(size_t)gr1 * D + c] =
                                    make_float2(o2 + ac.x * ic1, o3 + ac.y * ic1);
                            }
                        } else {
                            if (gr0 < M) red2(&g_acc[(size_t)sidx0 * D + c], o0, o1);
                            if (gr1 < M) red2(&g_acc[(size_t)sidx1 * D + c], o2, o3);
                        }
                    }
                }
                __syncthreads();
            }
        }
    }
}

// ---------------- bf16 hi/lo fused MLP (decoder: 3 layers + LN) ----------------
template <int NL>
__global__ void __launch_bounds__(256, 1) k_fused(
    const float* __restrict__ in,
    int slot0, int slot1, int slot2,
    const float* __restrict__ wb0, const float* __restrict__ wb1, const float* __restrict__ wb2,
    const float* __restrict__ lng, const float* __restrict__ lnb,
    float* __restrict__ out, int M, int nT)
{
    constexpr int OFF_AL = 34816;
    constexpr int OFF_W = 69632;
    constexpr int OFF_C = OFF_W + 69632;
    extern __shared__ char smem[];
    u32 sb = smem_u32(smem);

    int tid = threadIdx.x, lane = tid & 31, wid = tid >> 5;
    int wr = wid & 3, wc = wid >> 2, gid = lane >> 2, tig = lane & 3;

    float* sbias0 = (float*)(smem + OFF_C);
    float* sbias1 = (float*)(smem + OFF_C + 512);
    float* sbias2 = (float*)(smem + OFF_C + 1024);
    float* sg  = (float*)(smem + OFF_C + 1536);
    float* sl  = (float*)(smem + OFF_C + 2048);
    float* rs  = (float*)(smem + OFF_C + 2560);
    float* rq  = (float*)(smem + OFF_C + 3584);
    float* sbias[3] = {sbias0, sbias1, sbias2};

    int slots[3] = {slot0, slot1, slot2};
    const float* wbs[3] = {wb0, wb1, wb2};

    if (tid < 128) {
        #pragma unroll
        for (int l = 0; l < NL; l++) sbias[l][tid] = wbs[l][tid];
        sg[tid] = lng[tid]; sl[tid] = lnb[tid];
    }
    __syncthreads();

    u32 a_lo = (u32)((((lane & 7) + ((lane >> 3) & 1) * 8) * 136 + (lane >> 4) * 8) * 2);
    u32 b_lo = (u32)((((lane & 7) + ((lane >> 4) & 1) * 8) * 136 + ((lane >> 3) & 1) * 8) * 2);

    for (int t = blockIdx.x; t < nT; t += gridDim.x) {
        int tb = t * 128;

        for (int idx = tid; idx < 4096; idx += 256) {
            int row = idx >> 5, c4 = idx & 31;
            int gr = min(tb + row, M - 1);
            float4 v = ((const float4*)in)[(size_t)gr * 32 + c4];
            __nv_bfloat16 h0 = __float2bfloat16(v.x), h1 = __float2bfloat16(v.y);
            __nv_bfloat16 h2 = __float2bfloat16(v.z), h3 = __float2bfloat16(v.w);
            u32 hi01 = bfpack(h0, h1), hi23 = bfpack(h2, h3);
            u32 lo01 = bfpack(__float2bfloat16(v.x - __bfloat162float(h0)),
                              __float2bfloat16(v.y - __bfloat162float(h1)));
            u32 lo23 = bfpack(__float2bfloat16(v.z - __bfloat162float(h2)),
                              __float2bfloat16(v.w - __bfloat162float(h3)));
            *(uint2*)(smem + (size_t)(row * 136 + c4 * 4) * 2) = make_uint2(hi01, hi23);
            *(uint2*)(smem + OFF_AL + (size_t)(row * 136 + c4 * 4) * 2) = make_uint2(lo01, lo23);
        }
        __syncthreads();

        #pragma unroll
        for (int l = 0; l < NL; l++) {
            {
                const uint4* ph = ((const uint4*)g_whi) + (size_t)slots[l] * 2048;
                const uint4* pl = ((const uint4*)g_wlo) + (size_t)slots[l] * 2048;
                for (int i = tid; i < 2048; i += 256) {
                    int row = i >> 4, c = i & 15;
                    *(uint4*)(smem + OFF_W + row * 272 + c * 16) = ph[row * 16 + c];
                    *(uint4*)(smem + OFF_W + 34816 + row * 272 + c * 16) = pl[row * 16 + c];
                }
                __syncthreads();
            }

            float acc[2][8][4];
            #pragma unroll
            for (int i = 0; i < 2; i++)
                #pragma unroll
                for (int j = 0; j < 8; j++)
                    #pragma unroll
                    for (int k = 0; k < 4; k++) acc[i][j][k] = 0.f;

            u32 ab_hi = sb + (u32)(wr * 32 * 272) + a_lo;
            u32 ab_lo = ab_hi + OFF_AL;
            u32 bb_hi = sb + OFF_W + (u32)(wc * 64 * 272) + b_lo;
            u32 bb_lo = bb_hi + 34816;

            #pragma unroll
            for (int ks = 0; ks < 8; ks++) {
                u32 ah[2][4], alo[2][4];
                #pragma unroll
                for (int rt = 0; rt < 2; rt++) {
                    ldsm4(ab_hi + rt * (16 * 272) + ks * 32,
                          ah[rt][0], ah[rt][1], ah[rt][2], ah[rt][3]);
                    ldsm4(ab_lo + rt * (16 * 272) + ks * 32,
                          alo[rt][0], alo[rt][1], alo[rt][2], alo[rt][3]);
                }
                u32 bh[8][2], bl[8][2];
                #pragma unroll
                for (int np = 0; np < 4; np++) {
                    u32 r0, r1, r2, r3;
                    ldsm4(bb_hi + np * (16 * 272) + ks * 32, r0, r1, r2, r3);
                    bh[np * 2][0] = r0; bh[np * 2][1] = r1;
                    bh[np * 2 + 1][0] = r2; bh[np * 2 + 1][1] = r3;
                    ldsm4(bb_lo + np * (16 * 272) + ks * 32, r0, r1, r2, r3);
                    bl[np * 2][0] = r0; bl[np * 2][1] = r1;
                    bl[np * 2 + 1][0] = r2; bl[np * 2 + 1][1] = r3;
                }
                #pragma unroll
                for (int rt = 0; rt < 2; rt++)
                    #pragma unroll
                    for (int nt = 0; nt < 8; nt++) {
                        mma16816(acc[rt][nt], ah[rt], bh[nt]);
                        mma16816(acc[rt][nt], ah[rt], bl[nt]);
                        mma16816(acc[rt][nt], alo[rt], bh[nt]);
                    }
            }
            __syncthreads();

            if (l < NL - 1) {
                const float* bias = sbias[l];
                #pragma unroll
                for (int rt = 0; rt < 2; rt++) {
                    int r0 = wr * 32 + rt * 16 + gid;
                    #pragma unroll
                    for (int nt = 0; nt < 8; nt++) {
                        int c = wc * 64 + nt * 8 + tig * 2;
                        float b0v = bias[c], b1v = bias[c + 1];
                        float z0 = leaky(acc[rt][nt][0] + b0v);
                        float z1 = leaky(acc[rt][nt][1] + b1v);
                        float z2 = leaky(acc[rt][nt][2] + b0v);
                        float z3 = leaky(acc[rt][nt][3] + b1v);
                        __nv_bfloat16 h0 = __float2bfloat16(z0), h1 = __float2bfloat16(z1);
                        __nv_bfloat16 h2 = __float2bfloat16(z2), h3 = __float2bfloat16(z3);
                        *(u32*)(smem + (size_t)(r0 * 136 + c) * 2) = bfpack(h0, h1);
                        *(u32*)(smem + OFF_AL + (size_t)(r0 * 136 + c) * 2) =
                            bfpack(__float2bfloat16(z0 - __bfloat162float(h0)),
                                   __float2bfloat16(z1 - __bfloat162float(h1)));
                        *(u32*)(smem + (size_t)((r0 + 8) * 136 + c) * 2) = bfpack(h2, h3);
                        *(u32*)(smem + OFF_AL + (size_t)((r0 + 8) * 136 + c) * 2) =
                            bfpack(__float2bfloat16(z2 - __bfloat162float(h2)),
                                   __float2bfloat16(z3 - __bfloat162float(h3)));
                    }
                }
                __syncthreads();
            } else {
                const float* bias = sbias[NL - 1];
                #pragma unroll
                for (int rt = 0; rt < 2; rt++) {
                    float s0 = 0.f, q0 = 0.f, s1 = 0.f, q1 = 0.f;
                    #pragma unroll
                    for (int nt = 0; nt < 8; nt++) {
                        int c = wc * 64 + nt * 8 + tig * 2;
                        float b0v = bias[c], b1v = bias[c + 1];
                        float z0 = acc[rt][nt][0] + b0v, z1 = acc[rt][nt][1] + b1v;
                        float z2 = acc[rt][nt][2] + b0v, z3 = acc[rt][nt][3] + b1v;
                        s0 += z0 + z1; q0 += z0 * z0 + z1 * z1;
                        s1 += z2 + z3; q1 += z2 * z2 + z3 * z3;
                    }
                    s0 += __shfl_xor_sync(0xffffffffu, s0, 1);
                    q0 += __shfl_xor_sync(0xffffffffu, q0, 1);
                    s1 += __shfl_xor_sync(0xffffffffu, s1, 1);
                    q1 += __shfl_xor_sync(0xffffffffu, q1, 1);
                    s0 += __shfl_xor_sync(0xffffffffu, s0, 2);
                    q0 += __shfl_xor_sync(0xffffffffu, q0, 2);
                    s1 += __shfl_xor_sync(0xffffffffu, s1, 2);
                    q1 += __shfl_xor_sync(0xffffffffu, q1, 2);
                    int r0 = wr * 32 + rt * 16 + gid;
                    if (tig == 0) {
                        rs[r0 * 2 + wc] = s0; rq[r0 * 2 + wc] = q0;
                        rs[(r0 + 8) * 2 + wc] = s1; rq[(r0 + 8) * 2 + wc] = q1;
                    }
                }
                __syncthreads();
                #pragma unroll
                for (int rt = 0; rt < 2; rt++) {
                    int r0 = wr * 32 + rt * 16 + gid;
                    float S0 = rs[r0 * 2] + rs[r0 * 2 + 1];
                    float Q0 = rq[r0 * 2] + rq[r0 * 2 + 1];
                    float S1 = rs[(r0 + 8) * 2] + rs[(r0 + 8) * 2 + 1];
                    float Q1 = rq[(r0 + 8) * 2] + rq[(r0 + 8) * 2 + 1];
                    float m0 = S0 * (1.f / (float)D);
                    float i0 = rsqrtf(Q0 * (1.f / (float)D) - m0 * m0 + EPSf);
                    float m1 = S1 * (1.f / (float)D);
                    float i1 = rsqrtf(Q1 * (1.f / (float)D) - m1 * m1 + EPSf);
                    int gr0 = tb + r0, gr1 = gr0 + 8;
                    #pragma unroll
                    for (int nt = 0; nt < 8; nt++) {
                        int c = wc * 64 + nt * 8 + tig * 2;
                        float b0v = bias[c], b1v = bias[c + 1];
                        float g0 = sg[c], g1 = sg[c + 1];
                        float l0 = sl[c], l1 = sl[c + 1];
                        float o0 = (acc[rt][nt][0] + b0v - m0) * i0 * g0 + l0;
                        float o1 = (acc[rt][nt][1] + b1v - m0) * i0 * g1 + l1;
                        float o2 = (acc[rt][nt][2] + b0v - m1) * i1 * g0 + l0;
                        float o3 = (acc[rt][nt][3] + b1v - m1) * i1 * g1 + l1;
                        if (gr0 < M) *(float2*)&out[(size_t)gr0 * D + c] = make_float2(o0, o1);
                        if (gr1 < M) *(float2*)&out[(size_t)gr1 * D + c] = make_float2(o2, o3);
                    }
                }
                __syncthreads();
            }
        }
    }
}

// ---------------- host orchestration ----------------
extern "C" void kernel_launch(void* const* d_in, const int* in_sizes, int n_in,
                              void* d_out, int out_size)
{
    const float* node_feat = (const float*)d_in[0];
    const float* edge_feat = (const float*)d_in[1];
    const int*   ei        = (const int*)d_in[2];
    const float* enW1 = (const float*)d_in[3];  const float* enb1 = (const float*)d_in[4];
    const float* enW2 = (const float*)d_in[5];  const float* enb2 = (const float*)d_in[6];
    const float* enW3 = (const float*)d_in[7];  const float* enb3 = (const float*)d_in[8];
    const float* enlg = (const float*)d_in[9];  const float* enlb = (const float*)d_in[10];
    const float* eeW1 = (const float*)d_in[11]; const float* eeb1 = (const float*)d_in[12];
    const float* eeW2 = (const float*)d_in[13]; const float* eeb2 = (const float*)d_in[14];
    const float* eeW3 = (const float*)d_in[15]; const float* eeb3 = (const float*)d_in[16];
    const float* eelg = (const float*)d_in[17]; const float* eelb = (const float*)d_in[18];
    const float* procW = (const float*)d_in[19];
    const float* procb = (const float*)d_in[20];
    const float* bng   = (const float*)d_in[21];
    const float* bnb   = (const float*)d_in[22];
    const float* dW1 = (const float*)d_in[23]; const float* db1 = (const float*)d_in[24];
    const float* dW2 = (const float*)d_in[25]; const float* db2 = (const float*)d_in[26];
    const float* dW3 = (const float*)d_in[27]; const float* db3 = (const float*)d_in[28];
    const float* dlg = (const float*)d_in[29]; const float* dlb = (const float*)d_in[30];
    float* out = (float*)d_out;

    float* hn_ptr = nullptr; cudaGetSymbolAddress((void**)&hn_ptr, g_hn);
    float* y_ptr = nullptr;  cudaGetSymbolAddress((void**)&y_ptr, g_y);

    const int SM_EDGE16 = 34816 + 2 * 34816 + EDGE_IN * 512 + 5120;   // 111616
    const int SM_NODE16 = 34816 + 2 * 34816 + NODE_IN * 512 + 5120;   // 119296
    const int SM_DEC    = 69632 + 69632 + 5120;                        // 144384

    cudaFuncSetAttribute(k_f16<EDGE_IN, 1, 2>, cudaFuncAttributeMaxDynamicSharedMemorySize, SM_EDGE16);
    cudaFuncSetAttribute(k_f16<NODE_IN, 3, 1>, cudaFuncAttributeMaxDynamicSharedMemorySize, SM_NODE16);
    cudaFuncSetAttribute(k_fused<3>, cudaFuncAttributeMaxDynamicSharedMemorySize, SM_DEC);
    cudaFuncSetAttribute(k_conv<false>, cudaFuncAttributeMaxDynamicSharedMemorySize, SM_CONV);
    cudaFuncSetAttribute(k_conv<true>,  cudaFuncAttributeMaxDynamicSharedMemorySize, SM_CONV);

    int NnT = (Nn + 127) / 128, EeT = Ee / 128;
    int NnT64 = (Nn + 63) / 64;
    int G = 148, G2 = 296;

    // 1: weight splits   2: zero   3: count
    k_wsplit_all<<<dim3(64, NSLOT), 256>>>(enW2, enW3, eeW2, eeW3, procW, dW1, dW2, dW3);
    k_zero<<<512, 256>>>();
    k_count<<<(Ee + 255) / 256, 256>>>(ei);
    // 4: edge encoder (profiled) — fp16 single-pass, LN + scatter-sum into g_acc
    k_f16<EDGE_IN, 1, 2><<<G2, 256, SM_EDGE16>>>(
        edge_feat, 2, 3, eeb2, eeb3, eeW1, eeb1, eelg, eelb,
        nullptr, ei, Ee, EeT);
    // 5: node encoder — fp16 single-pass, LN + scatter-mean mix -> g_hn
    k_f16<NODE_IN, 3, 1><<<G, 256, SM_NODE16>>>(
        node_feat, 0, 1, enb2, enb3, enW1, enb1, enlg, enlb,
        hn_ptr, nullptr, Nn, NnT);
    // CSR build
    k_scan<<<1, 1024>>>();
    k_dis<<<(Nn + 255) / 256, 256>>>();
    k_fill<<<(Ee + 255) / 256, 256>>>(ei);

    // processor steps (bf16 hi/lo convs + CSR gathers)
    for (int s = 0; s < STEPS; s++) {
        const float* b0 = procb + (size_t)(s * 2 + 0) * D;
        const float* b1 = procb + (size_t)(s * 2 + 1) * D;

        k_conv<false><<<G2, 256, SM_CONV>>>(hn_ptr, 4 + 2 * s, 0, nullptr, nullptr, NnT64);
        k_gatherA<<<592, 256>>>(b0, s);
        k_conv<true><<<G2, 256, SM_CONV>>>(y_ptr, 5 + 2 * s, s,
                                           bng + (size_t)s * D, bnb + (size_t)s * D, NnT64);
        k_gatherB<<<592, 256>>>(b1);
    }

    // decoder (bf16 hi/lo, 3 layers + LN)
    k_fused<3><<<G, 256, SM_DEC>>>(
        hn_ptr, 14, 15, 16, db1, db2, db3,
        dlg, dlb, out, Nn, NnT);
}